// round 1
// baseline (speedup 1.0000x reference)
#include <cuda_runtime.h>
#include <cuda_bf16.h>
#include <math.h>

// Problem constants
#define B_  4
#define T_  2048
#define C_  1024
#define H_  16
#define N_  64
#define DMIX 32
#define DGATE 64
#define DDECAY 64

static const long BTC = (long)B_ * T_ * C_;   // 8388608

// ---------------- scratch (device globals; no runtime allocation) -------------
__device__ float g_xx [ (long)B_*T_*C_ ];
__device__ float g_xxx[ (long)B_*T_*C_ ];
__device__ float g_xw [ (long)B_*T_*C_ ];
__device__ float g_xk [ (long)B_*T_*C_ ];
__device__ float g_xv [ (long)B_*T_*C_ ];
__device__ float g_xr [ (long)B_*T_*C_ ];
__device__ float g_xg [ (long)B_*T_*C_ ];
__device__ float g_r  [ (long)B_*T_*C_ ];
__device__ float g_k  [ (long)B_*T_*C_ ];
__device__ float g_v  [ (long)B_*T_*C_ ];
__device__ float g_w  [ (long)B_*T_*C_ ];
__device__ float g_g  [ (long)B_*T_*C_ ];
__device__ float g_y  [ (long)B_*T_*C_ ];
__device__ float g_z  [ (long)B_*T_*C_ ];
__device__ float g_lora [ (long)B_*T_*5*DMIX ];
__device__ float g_small[ (long)B_*T_*64 ];

// ---------------- generic tiled fp32 GEMM: C = epi(A[M,K] @ B[K,N]) ----------
// BM=128, BN=128, BK=8, 256 threads, 8x8 microtile per thread.
// EPI: 0 = none, 1 = tanh, 2 = exp(-exp(x + bias[col]))
#define BM 128
#define BN 128
#define BKT 8

template<int EPI>
__global__ __launch_bounds__(256) void gemm_k(
    const float* __restrict__ A, int lda,
    const float* __restrict__ Bm, int ldb,
    float* __restrict__ Cm, int ldc,
    int M, int K, int Nn, const float* __restrict__ bias)
{
    __shared__ float As[BKT][BM + 4];
    __shared__ float Bs[BKT][BN];

    const int tid = threadIdx.x;
    const int tx = tid & 15;        // 0..15 -> col group
    const int ty = tid >> 4;        // 0..15 -> row group
    const int row0 = blockIdx.y * BM;
    const int col0 = blockIdx.x * BN;

    float acc[8][8];
    #pragma unroll
    for (int i = 0; i < 8; i++)
        #pragma unroll
        for (int j = 0; j < 8; j++) acc[i][j] = 0.f;

    for (int k0 = 0; k0 < K; k0 += BKT) {
        // load A tile (BM x BK), store transposed As[c][r]
        #pragma unroll
        for (int l = 0; l < 4; l++) {
            int e = tid + l * 256;
            int r = e >> 3, c = e & 7;
            As[c][r] = A[(long)(row0 + r) * lda + (k0 + c)];
        }
        // load B tile (BK x BN)
        #pragma unroll
        for (int l = 0; l < 4; l++) {
            int e = tid + l * 256;
            int r = e >> 7, c = e & 127;
            int gc = col0 + c;
            Bs[r][c] = (gc < Nn) ? Bm[(long)(k0 + r) * ldb + gc] : 0.f;
        }
        __syncthreads();

        #pragma unroll
        for (int kk = 0; kk < BKT; kk++) {
            float a[8], b[8];
            *(float4*)(a)     = *(const float4*)&As[kk][ty * 8];
            *(float4*)(a + 4) = *(const float4*)&As[kk][ty * 8 + 4];
            *(float4*)(b)     = *(const float4*)&Bs[kk][tx * 8];
            *(float4*)(b + 4) = *(const float4*)&Bs[kk][tx * 8 + 4];
            #pragma unroll
            for (int i = 0; i < 8; i++)
                #pragma unroll
                for (int j = 0; j < 8; j++)
                    acc[i][j] = fmaf(a[i], b[j], acc[i][j]);
        }
        __syncthreads();
    }

    #pragma unroll
    for (int i = 0; i < 8; i++) {
        int gr = row0 + ty * 8 + i;
        #pragma unroll
        for (int j = 0; j < 8; j++) {
            int gc = col0 + tx * 8 + j;
            if (gc < Nn) {
                float vv = acc[i][j];
                if (EPI == 1) vv = tanhf(vv);
                else if (EPI == 2) { vv += bias[gc]; vv = expf(-expf(vv)); }
                Cm[(long)gr * ldc + gc] = vv;
            }
        }
    }
}

// ---------------- elementwise: time shift + maa_x mix ------------------------
__global__ void shift_kernel(const float* __restrict__ x,
                             const float* __restrict__ maa_x,
                             float* __restrict__ xx, float* __restrict__ xxx,
                             long total)
{
    long idx = (long)blockIdx.x * blockDim.x + threadIdx.x;
    if (idx >= total) return;
    int c = (int)(idx % C_);
    long rt = idx / C_;
    int t = (int)(rt % T_);
    float xv = x[idx];
    float xp = (t > 0) ? x[idx - C_] : 0.f;
    float d = xp - xv;
    xx[idx] = d;
    xxx[idx] = xv + d * maa_x[c];
}

// ---------------- elementwise: xw..xg = x + xx*(maa_? + m_?) in-place --------
__global__ void fuse5_kernel(const float* __restrict__ x, const float* __restrict__ xx,
    const float* __restrict__ mw, const float* __restrict__ mk,
    const float* __restrict__ mv, const float* __restrict__ mr,
    const float* __restrict__ mg,
    float* __restrict__ xw, float* __restrict__ xk, float* __restrict__ xv_,
    float* __restrict__ xr, float* __restrict__ xg, long total)
{
    long idx = (long)blockIdx.x * blockDim.x + threadIdx.x;
    if (idx >= total) return;
    int c = (int)(idx % C_);
    float xi = x[idx], d = xx[idx];
    xw[idx]  = fmaf(d, mw[c] + xw[idx],  xi);
    xk[idx]  = fmaf(d, mk[c] + xk[idx],  xi);
    xv_[idx] = fmaf(d, mv[c] + xv_[idx], xi);
    xr[idx]  = fmaf(d, mr[c] + xr[idx],  xi);
    xg[idx]  = fmaf(d, mg[c] + xg[idx],  xi);
}

// ---------------- WKV6 recurrence --------------------------------------------
// grid = B*H blocks, 256 threads: j = tid&63 (value dim), q = tid>>6 (key-dim
// quarter). Each thread holds 16 state rows in registers. r/k/w/u packed as
// float4 in SMEM (1 LDS.128 per inner iter). One-step register prefetch to
// overlap DRAM latency with compute.
__global__ __launch_bounds__(256) void wkv_kernel(
    const float* __restrict__ r, const float* __restrict__ k,
    const float* __restrict__ v, const float* __restrict__ w,
    const float* __restrict__ u, float* __restrict__ y)
{
    __shared__ float4 srkwu[64];
    __shared__ float red[256];

    const int tid = threadIdx.x;
    const int j = tid & 63;
    const int q = tid >> 6;
    const int b = blockIdx.x / H_;
    const int h = blockIdx.x % H_;

    const float uj = u[h * 64 + j];
    float s[16];
    #pragma unroll
    for (int i = 0; i < 16; i++) s[i] = 0.f;

    long idx = ((long)b * T_) * C_ + h * 64;
    float rr = 0.f, kk = 0.f, ww = 0.f;
    if (q == 0) { rr = r[idx + j]; kk = k[idx + j]; ww = w[idx + j]; }
    float vv = v[idx + j];

    for (int t = 0; t < T_; t++) {
        if (q == 0) srkwu[j] = make_float4(rr, kk, ww, uj);
        float vj = vv;
        __syncthreads();

        // prefetch next timestep while computing this one
        long idx2 = idx + C_;
        if (t + 1 < T_) {
            if (q == 0) { rr = r[idx2 + j]; kk = k[idx2 + j]; ww = w[idx2 + j]; }
            vv = v[idx2 + j];
        }

        float yp = 0.f;
        #pragma unroll
        for (int ii = 0; ii < 16; ii++) {
            float4 p = srkwu[q * 16 + ii];
            float kv = p.y * vj;
            yp += p.x * fmaf(p.w, kv, s[ii]);     // r*(S + u*kv)
            s[ii] = fmaf(p.z, s[ii], kv);         // S = w*S + kv
        }
        red[tid] = yp;
        __syncthreads();
        if (q == 0)
            y[idx + j] = red[j] + red[64 + j] + red[128 + j] + red[192 + j];
        idx = idx2;
    }
}

// ---------------- GroupNorm over heads + gate multiply -----------------------
// grid = B*T, block = 512 (one warp per head, 2 elems per lane)
__global__ __launch_bounds__(512) void gn_kernel(
    const float* __restrict__ y, const float* __restrict__ ln_g,
    const float* __restrict__ ln_b, const float* __restrict__ g,
    float* __restrict__ z)
{
    const int bt = blockIdx.x;
    const int warp = threadIdx.x >> 5;
    const int lane = threadIdx.x & 31;
    const long base = (long)bt * C_ + warp * 64;

    float a0 = y[base + lane];
    float a1 = y[base + 32 + lane];
    float sum = a0 + a1;
    float sq = a0 * a0 + a1 * a1;
    #pragma unroll
    for (int off = 16; off > 0; off >>= 1) {
        sum += __shfl_xor_sync(0xffffffffu, sum, off);
        sq  += __shfl_xor_sync(0xffffffffu, sq,  off);
    }
    float mu = sum * (1.f / 64.f);
    float var = sq * (1.f / 64.f) - mu * mu;
    float inv = rsqrtf(var + 6.4e-4f);

    int c0 = warp * 64 + lane;
    float z0 = (a0 - mu) * inv * ln_g[c0] + ln_b[c0];
    float z1 = (a1 - mu) * inv * ln_g[c0 + 32] + ln_b[c0 + 32];
    z[base + lane]      = z0 * g[base + lane];
    z[base + 32 + lane] = z1 * g[base + 32 + lane];
}

// ---------------- launcher ----------------------------------------------------
extern "C" void kernel_launch(void* const* d_in, const int* in_sizes, int n_in,
                              void* d_out, int out_size)
{
    const float* x          = (const float*)d_in[0];
    const float* maa_x      = (const float*)d_in[1];
    const float* maa_w      = (const float*)d_in[2];
    const float* maa_k      = (const float*)d_in[3];
    const float* maa_v      = (const float*)d_in[4];
    const float* maa_r      = (const float*)d_in[5];
    const float* maa_g      = (const float*)d_in[6];
    const float* maa_w1     = (const float*)d_in[7];   // [C, 160]
    const float* maa_w2     = (const float*)d_in[8];   // [5, 32, C]
    const float* Wr         = (const float*)d_in[9];
    const float* Wk         = (const float*)d_in[10];
    const float* Wv         = (const float*)d_in[11];
    const float* Wo         = (const float*)d_in[12];
    const float* gate_w1    = (const float*)d_in[13];  // [C, 64]
    const float* gate_w2    = (const float*)d_in[14];  // [64, C]
    const float* time_decay = (const float*)d_in[15];  // [C]
    const float* decay_w1   = (const float*)d_in[16];  // [C, 64]
    const float* decay_w2   = (const float*)d_in[17];  // [64, C]
    const float* u          = (const float*)d_in[18];  // [H, 64]
    const float* ln_g       = (const float*)d_in[19];
    const float* ln_b       = (const float*)d_in[20];
    (void)in_sizes; (void)n_in; (void)out_size;

    float *p_xx, *p_xxx, *p_xw, *p_xk, *p_xv, *p_xr, *p_xg;
    float *p_r, *p_k, *p_v, *p_w, *p_g, *p_y, *p_z, *p_lora, *p_small;
    cudaGetSymbolAddress((void**)&p_xx, g_xx);
    cudaGetSymbolAddress((void**)&p_xxx, g_xxx);
    cudaGetSymbolAddress((void**)&p_xw, g_xw);
    cudaGetSymbolAddress((void**)&p_xk, g_xk);
    cudaGetSymbolAddress((void**)&p_xv, g_xv);
    cudaGetSymbolAddress((void**)&p_xr, g_xr);
    cudaGetSymbolAddress((void**)&p_xg, g_xg);
    cudaGetSymbolAddress((void**)&p_r, g_r);
    cudaGetSymbolAddress((void**)&p_k, g_k);
    cudaGetSymbolAddress((void**)&p_v, g_v);
    cudaGetSymbolAddress((void**)&p_w, g_w);
    cudaGetSymbolAddress((void**)&p_g, g_g);
    cudaGetSymbolAddress((void**)&p_y, g_y);
    cudaGetSymbolAddress((void**)&p_z, g_z);
    cudaGetSymbolAddress((void**)&p_lora, g_lora);
    cudaGetSymbolAddress((void**)&p_small, g_small);

    const long total = BTC;
    const int M = B_ * T_;          // 8192
    const int gy = M / BM;          // 64

    // 1. time shift + maa_x mix
    shift_kernel<<<(int)((total + 255) / 256), 256>>>(x, maa_x, p_xx, p_xxx, total);

    // 2. lora = tanh(xxx @ maa_w1)   [8192,1024]@[1024,160]
    gemm_k<1><<<dim3(2, gy), 256>>>(p_xxx, C_, maa_w1, 5 * DMIX,
                                    p_lora, 5 * DMIX, M, C_, 5 * DMIX, nullptr);

    // 3. m_f = lora[:, f] @ maa_w2[f]   five [8192,32]@[32,1024] GEMMs
    float* mixout[5] = { p_xw, p_xk, p_xv, p_xr, p_xg };
    for (int f = 0; f < 5; f++)
        gemm_k<0><<<dim3(8, gy), 256>>>(p_lora + f * DMIX, 5 * DMIX,
                                        maa_w2 + (long)f * DMIX * C_, C_,
                                        mixout[f], C_, M, DMIX, C_, nullptr);

    // 4. xw..xg = x + xx*(maa_? + m_?)  (in place)
    const float* maas[5] = { maa_w, maa_k, maa_v, maa_r, maa_g };
    fuse5_kernel<<<(int)((total + 255) / 256), 256>>>(x, p_xx,
        maas[0], maas[1], maas[2], maas[3], maas[4],
        p_xw, p_xk, p_xv, p_xr, p_xg, total);

    // 5. r, k, v projections  [8192,1024]@[1024,1024]
    gemm_k<0><<<dim3(8, gy), 256>>>(p_xr, C_, Wr, C_, p_r, C_, M, C_, C_, nullptr);
    gemm_k<0><<<dim3(8, gy), 256>>>(p_xk, C_, Wk, C_, p_k, C_, M, C_, C_, nullptr);
    gemm_k<0><<<dim3(8, gy), 256>>>(p_xv, C_, Wv, C_, p_v, C_, M, C_, C_, nullptr);

    // 6. decay: w = exp(-exp(time_decay + tanh(xw@decay_w1)@decay_w2))
    gemm_k<1><<<dim3(1, gy), 256>>>(p_xw, C_, decay_w1, DDECAY,
                                    p_small, DDECAY, M, C_, DDECAY, nullptr);
    gemm_k<2><<<dim3(8, gy), 256>>>(p_small, DDECAY, decay_w2, C_,
                                    p_w, C_, M, DDECAY, C_, time_decay);

    // 7. WKV6 recurrence
    wkv_kernel<<<B_ * H_, 256>>>(p_r, p_k, p_v, p_w, u, p_y);

    // 8. gate: g = tanh(xg@gate_w1)@gate_w2
    gemm_k<1><<<dim3(1, gy), 256>>>(p_xg, C_, gate_w1, DGATE,
                                    p_small, DGATE, M, C_, DGATE, nullptr);
    gemm_k<0><<<dim3(8, gy), 256>>>(p_small, DGATE, gate_w2, C_,
                                    p_g, C_, M, DGATE, C_, nullptr);

    // 9. GroupNorm over heads + gate multiply
    gn_kernel<<<M, 512>>>(p_y, ln_g, ln_b, p_g, p_z);

    // 10. out = z @ Wo
    gemm_k<0><<<dim3(8, gy), 256>>>(p_z, C_, Wo, C_, (float*)d_out, C_,
                                    M, C_, C_, nullptr);
}

// round 2
// speedup vs baseline: 1.1888x; 1.1888x over previous
#include <cuda_runtime.h>
#include <cuda_bf16.h>
#include <math.h>

// Problem constants
#define B_  4
#define T_  2048
#define C_  1024
#define H_  16
#define N_  64
#define DMIX 32
#define DGATE 64
#define DDECAY 64

#define CHUNK 64
#define G_ 32                     // chunks per (b,h)
#define NCHUNK (B_*H_*G_)         // 2048
#define STRD 68                   // padded row stride for chunk smem tiles

static const long BTC = (long)B_ * T_ * C_;   // 8388608

// ---------------- scratch (device globals; no runtime allocation) -------------
__device__ float g_xx [ (long)B_*T_*C_ ];
__device__ float g_xxx[ (long)B_*T_*C_ ];
__device__ float g_xw [ (long)B_*T_*C_ ];
__device__ float g_xk [ (long)B_*T_*C_ ];
__device__ float g_xv [ (long)B_*T_*C_ ];
__device__ float g_xr [ (long)B_*T_*C_ ];
__device__ float g_xg [ (long)B_*T_*C_ ];
__device__ float g_r  [ (long)B_*T_*C_ ];
__device__ float g_k  [ (long)B_*T_*C_ ];
__device__ float g_v  [ (long)B_*T_*C_ ];
__device__ float g_w  [ (long)B_*T_*C_ ];   // stores lw = log(decay) = -exp(wraw)
__device__ float g_g  [ (long)B_*T_*C_ ];
__device__ float g_y  [ (long)B_*T_*C_ ];
__device__ float g_z  [ (long)B_*T_*C_ ];
__device__ float g_lora [ (long)B_*T_*5*DMIX ];
__device__ float g_small[ (long)B_*T_*64 ];
__device__ float g_D  [ (long)NCHUNK*64*64 ];   // per-chunk state delta
__device__ float g_Sc [ (long)NCHUNK*64*64 ];   // state at chunk start
__device__ float g_rp [ (long)NCHUNK*64*64 ];   // r' transposed [chunk][i][t]
__device__ float g_pL [ (long)NCHUNK*64 ];      // per-chunk total log-decay

// ---------------- generic tiled fp32 GEMM: C = epi(A[M,K] @ B[K,N]) ----------
#define BM 128
#define BN 128
#define BKT 8

// EPI: 0 = none, 1 = tanh, 2 = log-decay: -exp(x + bias[col])
template<int EPI>
__global__ __launch_bounds__(256) void gemm_k(
    const float* __restrict__ A, int lda,
    const float* __restrict__ Bm, int ldb,
    float* __restrict__ Cm, int ldc,
    int M, int K, int Nn, const float* __restrict__ bias)
{
    __shared__ float As[BKT][BM + 4];
    __shared__ float Bs[BKT][BN];

    const int tid = threadIdx.x;
    const int tx = tid & 15;
    const int ty = tid >> 4;
    const int row0 = blockIdx.y * BM;
    const int col0 = blockIdx.x * BN;

    float acc[8][8];
    #pragma unroll
    for (int i = 0; i < 8; i++)
        #pragma unroll
        for (int j = 0; j < 8; j++) acc[i][j] = 0.f;

    for (int k0 = 0; k0 < K; k0 += BKT) {
        #pragma unroll
        for (int l = 0; l < 4; l++) {
            int e = tid + l * 256;
            int r = e >> 3, c = e & 7;
            As[c][r] = A[(long)(row0 + r) * lda + (k0 + c)];
        }
        #pragma unroll
        for (int l = 0; l < 4; l++) {
            int e = tid + l * 256;
            int r = e >> 7, c = e & 127;
            int gc = col0 + c;
            Bs[r][c] = (gc < Nn) ? Bm[(long)(k0 + r) * ldb + gc] : 0.f;
        }
        __syncthreads();

        #pragma unroll
        for (int kk = 0; kk < BKT; kk++) {
            float a[8], b[8];
            *(float4*)(a)     = *(const float4*)&As[kk][ty * 8];
            *(float4*)(a + 4) = *(const float4*)&As[kk][ty * 8 + 4];
            *(float4*)(b)     = *(const float4*)&Bs[kk][tx * 8];
            *(float4*)(b + 4) = *(const float4*)&Bs[kk][tx * 8 + 4];
            #pragma unroll
            for (int i = 0; i < 8; i++)
                #pragma unroll
                for (int j = 0; j < 8; j++)
                    acc[i][j] = fmaf(a[i], b[j], acc[i][j]);
        }
        __syncthreads();
    }

    #pragma unroll
    for (int i = 0; i < 8; i++) {
        int gr = row0 + ty * 8 + i;
        #pragma unroll
        for (int j = 0; j < 8; j++) {
            int gc = col0 + tx * 8 + j;
            if (gc < Nn) {
                float vv = acc[i][j];
                if (EPI == 1) vv = tanhf(vv);
                else if (EPI == 2) vv = -expf(vv + bias[gc]);
                Cm[(long)gr * ldc + gc] = vv;
            }
        }
    }
}

// ---------------- elementwise: time shift + maa_x mix ------------------------
__global__ void shift_kernel(const float* __restrict__ x,
                             const float* __restrict__ maa_x,
                             float* __restrict__ xx, float* __restrict__ xxx,
                             long total)
{
    long idx = (long)blockIdx.x * blockDim.x + threadIdx.x;
    if (idx >= total) return;
    int c = (int)(idx % C_);
    long rt = idx / C_;
    int t = (int)(rt % T_);
    float xv = x[idx];
    float xp = (t > 0) ? x[idx - C_] : 0.f;
    float d = xp - xv;
    xx[idx] = d;
    xxx[idx] = xv + d * maa_x[c];
}

// ---------------- fused: m_f = lora_f @ w2_f; x_f = x + xx*(maa_f + m_f) -----
// grid (M/32, C/128), 256 threads. Computes all 5 branches in one pass.
__global__ __launch_bounds__(256) void mix5_fuse(
    const float* __restrict__ lora,     // [M,160]
    const float* __restrict__ w2,       // [5,32,1024]
    const float* __restrict__ x, const float* __restrict__ xx,
    const float* __restrict__ maa_w, const float* __restrict__ maa_k,
    const float* __restrict__ maa_v, const float* __restrict__ maa_r,
    const float* __restrict__ maa_g,
    float* __restrict__ xw, float* __restrict__ xk, float* __restrict__ xv_,
    float* __restrict__ xr, float* __restrict__ xg)
{
    __shared__ float ls[32 * 160];
    __shared__ float ws[32 * 128];

    const int tid = threadIdx.x;
    const int rb = blockIdx.x * 32;
    const int cb = blockIdx.y * 128;

    for (int e = tid; e < 32 * 160; e += 256)
        ls[e] = lora[(long)(rb + e / 160) * 160 + (e % 160)];

    const int r = tid >> 3;             // 0..31
    const int j0 = (tid & 7) * 16;      // 0..112

    const long gbase = (long)(rb + r) * C_ + cb + j0;
    float xvv[16], xxv[16];
    #pragma unroll
    for (int jj = 0; jj < 16; jj += 4) {
        *(float4*)&xvv[jj] = *(const float4*)&x[gbase + jj];
        *(float4*)&xxv[jj] = *(const float4*)&xx[gbase + jj];
    }

    const float* maas[5] = { maa_w, maa_k, maa_v, maa_r, maa_g };
    float* outs[5] = { xw, xk, xv_, xr, xg };

    #pragma unroll
    for (int f = 0; f < 5; f++) {
        __syncthreads();
        for (int e = tid; e < 32 * 128; e += 256)
            ws[e] = w2[((long)f * 32 + e / 128) * 1024 + cb + (e & 127)];
        __syncthreads();

        float acc[16];
        #pragma unroll
        for (int jj = 0; jj < 16; jj++) acc[jj] = 0.f;
        #pragma unroll 8
        for (int d = 0; d < 32; d++) {
            float lv = ls[r * 160 + f * 32 + d];
            #pragma unroll
            for (int jj = 0; jj < 16; jj++)
                acc[jj] = fmaf(lv, ws[d * 128 + j0 + jj], acc[jj]);
        }
        const float* ma = maas[f];
        float* outp = outs[f];
        #pragma unroll
        for (int jj = 0; jj < 16; jj++) {
            float mm = ma[cb + j0 + jj] + acc[jj];
            acc[jj] = fmaf(xxv[jj], mm, xvv[jj]);
        }
        #pragma unroll
        for (int jj = 0; jj < 16; jj += 4)
            *(float4*)&outp[gbase + jj] = *(float4*)&acc[jj];
    }
}

// ---------------- chunked WKV6 -----------------------------------------------
// Pass A: per-chunk intra work. grid NCHUNK, 256 threads, dynamic smem.
__global__ __launch_bounds__(256) void wkv_chunkA(
    const float* __restrict__ r, const float* __restrict__ k,
    const float* __restrict__ v, const float* __restrict__ lw,
    const float* __restrict__ u,
    float* __restrict__ y, float* __restrict__ Dout,
    float* __restrict__ rpout, float* __restrict__ pLout)
{
    extern __shared__ float sm[];
    float* lp   = sm;                   // [65][64]  exclusive log-cumsum
    float* bufA = lp + 65 * 64;         // [64][STRD] lw first, AT later
    float* rpT  = bufA + 64 * STRD;     // [i][t]
    float* kpT  = rpT + 64 * STRD;      // [i][t]
    float* kpp  = kpT + 64 * STRD;      // [s][i]
    float* vsm  = kpp + 64 * STRD;      // [s][j]
    float* dsm  = vsm + 64 * STRD;      // [64] diag terms
    float* usm  = dsm + 64;             // [64]

    const int tid = threadIdx.x;
    const int chunk = blockIdx.x;
    const int bh = chunk >> 5;
    const int c  = chunk & 31;
    const int b = bh >> 4, h = bh & 15;
    const long base = ((long)b * T_ + c * CHUNK) * C_ + h * 64;

    if (tid < 64) usm[tid] = u[h * 64 + tid];

    const int i  = tid & 63;
    const int tq = tid >> 6;

    // 1. load lw chunk into bufA [t][STRD]
    #pragma unroll
    for (int e = 0; e < 16; e++) {
        int t = tq + 4 * e;
        bufA[t * STRD + i] = lw[base + (long)t * C_ + i];
    }
    __syncthreads();

    // 2. exclusive cumsum along t per channel (threads 0..63)
    if (tid < 64) {
        float run = 0.f;
        for (int t = 0; t < 64; t++) {
            lp[t * 64 + tid] = run;
            run += bufA[t * STRD + tid];
        }
        lp[64 * 64 + tid] = run;
        pLout[(long)chunk * 64 + tid] = run;
    }
    __syncthreads();

    // 3. build scaled operands + diag
    #pragma unroll
    for (int e = 0; e < 16; e++) {
        int t = tq + 4 * e;
        long gi = base + (long)t * C_ + i;
        float rr = r[gi], kk = k[gi];
        float lpti = lp[t * 64 + i];
        float lpn  = lpti + bufA[t * STRD + i];
        float lpL  = lp[64 * 64 + i];
        rpT[i * STRD + t] = rr * __expf(lpti);
        kpT[i * STRD + t] = kk * __expf(-lpn);
        kpp[t * STRD + i] = kk * __expf(lpL - lpn);
        vsm[t * STRD + i] = v[gi];
    }
    {   // diag[t] = sum_i r_t u_i k_t   (4 threads per t)
        int t = tid >> 2, q = tid & 3;
        long gb = base + (long)t * C_;
        float p = 0.f;
        #pragma unroll
        for (int ii = 0; ii < 16; ii++) {
            int ci = q * 16 + ii;
            p += r[gb + ci] * usm[ci] * k[gb + ci];
        }
        p += __shfl_xor_sync(0xffffffffu, p, 1);
        p += __shfl_xor_sync(0xffffffffu, p, 2);
        if (q == 0) dsm[t] = p;
    }
    __syncthreads();

    // 4. persist r' (layout [chunk][i][t], coalesced)
    {
        float* rpg = rpout + (long)chunk * 64 * 64;
        #pragma unroll
        for (int e = 0; e < 16; e++) {
            int flat = tid + 256 * e;
            rpg[flat] = rpT[(flat >> 6) * STRD + (flat & 63)];
        }
    }

    // 5. A[t][s] = sum_i rpT[i][t]*kpT[i][s]; mask; store transposed AT[s][t]
    {
        int t0 = (tid >> 4) * 4, s0 = (tid & 15) * 4;
        float acc[4][4];
        #pragma unroll
        for (int a = 0; a < 4; a++)
            #pragma unroll
            for (int bq = 0; bq < 4; bq++) acc[a][bq] = 0.f;
        for (int ii = 0; ii < 64; ii++) {
            float4 a4 = *(const float4*)&rpT[ii * STRD + t0];
            float4 b4 = *(const float4*)&kpT[ii * STRD + s0];
            float av[4] = { a4.x, a4.y, a4.z, a4.w };
            float bv[4] = { b4.x, b4.y, b4.z, b4.w };
            #pragma unroll
            for (int a = 0; a < 4; a++)
                #pragma unroll
                for (int bq = 0; bq < 4; bq++)
                    acc[a][bq] = fmaf(av[a], bv[bq], acc[a][bq]);
        }
        __syncthreads();   // everyone done reading bufA-as-lw? (lw no longer needed; ensure step-3 readers done)
        #pragma unroll
        for (int a = 0; a < 4; a++)
            #pragma unroll
            for (int bq = 0; bq < 4; bq++) {
                int tt = t0 + a, ss = s0 + bq;
                float val = (tt > ss) ? acc[a][bq] : ((tt == ss) ? dsm[tt] : 0.f);
                bufA[ss * STRD + tt] = val;
            }
    }
    __syncthreads();

    // 6. Y_intra[t][j] = sum_s AT[s][t] * V[s][j]
    {
        int t0 = (tid >> 4) * 4, j0 = (tid & 15) * 4;
        float acc[4][4];
        #pragma unroll
        for (int a = 0; a < 4; a++)
            #pragma unroll
            for (int bq = 0; bq < 4; bq++) acc[a][bq] = 0.f;
        for (int s = 0; s < 64; s++) {
            float4 a4 = *(const float4*)&bufA[s * STRD + t0];
            float4 b4 = *(const float4*)&vsm[s * STRD + j0];
            float av[4] = { a4.x, a4.y, a4.z, a4.w };
            float bv[4] = { b4.x, b4.y, b4.z, b4.w };
            #pragma unroll
            for (int a = 0; a < 4; a++)
                #pragma unroll
                for (int bq = 0; bq < 4; bq++)
                    acc[a][bq] = fmaf(av[a], bv[bq], acc[a][bq]);
        }
        #pragma unroll
        for (int a = 0; a < 4; a++) {
            float4 o = make_float4(acc[a][0], acc[a][1], acc[a][2], acc[a][3]);
            *(float4*)&y[base + (long)(t0 + a) * C_ + j0] = o;
        }
    }

    // 7. D[i][j] = sum_s kpp[s][i] * V[s][j]
    {
        int i0 = (tid >> 4) * 4, j0 = (tid & 15) * 4;
        float acc[4][4];
        #pragma unroll
        for (int a = 0; a < 4; a++)
            #pragma unroll
            for (int bq = 0; bq < 4; bq++) acc[a][bq] = 0.f;
        for (int s = 0; s < 64; s++) {
            float4 a4 = *(const float4*)&kpp[s * STRD + i0];
            float4 b4 = *(const float4*)&vsm[s * STRD + j0];
            float av[4] = { a4.x, a4.y, a4.z, a4.w };
            float bv[4] = { b4.x, b4.y, b4.z, b4.w };
            #pragma unroll
            for (int a = 0; a < 4; a++)
                #pragma unroll
                for (int bq = 0; bq < 4; bq++)
                    acc[a][bq] = fmaf(av[a], bv[bq], acc[a][bq]);
        }
        float* Dp = Dout + (long)chunk * 4096;
        #pragma unroll
        for (int a = 0; a < 4; a++) {
            float4 o = make_float4(acc[a][0], acc[a][1], acc[a][2], acc[a][3]);
            *(float4*)&Dp[(i0 + a) * 64 + j0] = o;
        }
    }
}

// Pass B: sequential chunk-state scan. grid B*H, 256 threads.
__global__ __launch_bounds__(256) void wkv_chunkB(
    const float* __restrict__ D, const float* __restrict__ pL,
    float* __restrict__ S)
{
    const int bh = blockIdx.x;
    const int tid = threadIdx.x;
    const int i = tid >> 2;
    const int jb = (tid & 3) * 16;

    float4 s0 = {0,0,0,0}, s1 = {0,0,0,0}, s2 = {0,0,0,0}, s3 = {0,0,0,0};
    for (int c = 0; c < G_; c++) {
        long chunk = (long)bh * G_ + c;
        long off = chunk * 4096 + i * 64 + jb;
        *(float4*)&S[off + 0]  = s0;
        *(float4*)&S[off + 4]  = s1;
        *(float4*)&S[off + 8]  = s2;
        *(float4*)&S[off + 12] = s3;
        float pl = __expf(pL[chunk * 64 + i]);
        float4 d0 = *(const float4*)&D[off + 0];
        float4 d1 = *(const float4*)&D[off + 4];
        float4 d2 = *(const float4*)&D[off + 8];
        float4 d3 = *(const float4*)&D[off + 12];
        s0 = make_float4(fmaf(pl, s0.x, d0.x), fmaf(pl, s0.y, d0.y), fmaf(pl, s0.z, d0.z), fmaf(pl, s0.w, d0.w));
        s1 = make_float4(fmaf(pl, s1.x, d1.x), fmaf(pl, s1.y, d1.y), fmaf(pl, s1.z, d1.z), fmaf(pl, s1.w, d1.w));
        s2 = make_float4(fmaf(pl, s2.x, d2.x), fmaf(pl, s2.y, d2.y), fmaf(pl, s2.z, d2.z), fmaf(pl, s2.w, d2.w));
        s3 = make_float4(fmaf(pl, s3.x, d3.x), fmaf(pl, s3.y, d3.y), fmaf(pl, s3.z, d3.z), fmaf(pl, s3.w, d3.w));
    }
}

// Pass C: inter-chunk output  y += r' @ S_start. grid NCHUNK, 256 threads.
__global__ __launch_bounds__(256) void wkv_chunkC(
    const float* __restrict__ rp, const float* __restrict__ S,
    float* __restrict__ y)
{
    __shared__ float rps[64 * 64];
    __shared__ float Ss[64 * 64];

    const int tid = threadIdx.x;
    const int chunk = blockIdx.x;
    const int bh = chunk >> 5;
    const int c  = chunk & 31;
    const int b = bh >> 4, h = bh & 15;
    const long base = ((long)b * T_ + c * CHUNK) * C_ + h * 64;

    const float* rpg = rp + (long)chunk * 4096;
    const float* Sg  = S  + (long)chunk * 4096;
    #pragma unroll
    for (int e = 0; e < 4; e++) {
        int f4 = tid + 256 * e;
        *(float4*)&rps[f4 * 4] = *(const float4*)&rpg[f4 * 4];
        *(float4*)&Ss[f4 * 4]  = *(const float4*)&Sg[f4 * 4];
    }
    __syncthreads();

    int t0 = (tid >> 4) * 4, j0 = (tid & 15) * 4;
    float acc[4][4];
    #pragma unroll
    for (int a = 0; a < 4; a++)
        #pragma unroll
        for (int bq = 0; bq < 4; bq++) acc[a][bq] = 0.f;
    for (int ii = 0; ii < 64; ii++) {
        float4 a4 = *(const float4*)&rps[ii * 64 + t0];
        float4 b4 = *(const float4*)&Ss[ii * 64 + j0];
        float av[4] = { a4.x, a4.y, a4.z, a4.w };
        float bv[4] = { b4.x, b4.y, b4.z, b4.w };
        #pragma unroll
        for (int a = 0; a < 4; a++)
            #pragma unroll
            for (int bq = 0; bq < 4; bq++)
                acc[a][bq] = fmaf(av[a], bv[bq], acc[a][bq]);
    }
    #pragma unroll
    for (int a = 0; a < 4; a++) {
        long yo = base + (long)(t0 + a) * C_ + j0;
        float4 cur = *(const float4*)&y[yo];
        cur.x += acc[a][0]; cur.y += acc[a][1];
        cur.z += acc[a][2]; cur.w += acc[a][3];
        *(float4*)&y[yo] = cur;
    }
}

// ---------------- GroupNorm over heads + gate multiply -----------------------
__global__ __launch_bounds__(512) void gn_kernel(
    const float* __restrict__ y, const float* __restrict__ ln_g,
    const float* __restrict__ ln_b, const float* __restrict__ g,
    float* __restrict__ z)
{
    const int bt = blockIdx.x;
    const int warp = threadIdx.x >> 5;
    const int lane = threadIdx.x & 31;
    const long base = (long)bt * C_ + warp * 64;

    float a0 = y[base + lane];
    float a1 = y[base + 32 + lane];
    float sum = a0 + a1;
    float sq = a0 * a0 + a1 * a1;
    #pragma unroll
    for (int off = 16; off > 0; off >>= 1) {
        sum += __shfl_xor_sync(0xffffffffu, sum, off);
        sq  += __shfl_xor_sync(0xffffffffu, sq,  off);
    }
    float mu = sum * (1.f / 64.f);
    float var = sq * (1.f / 64.f) - mu * mu;
    float inv = rsqrtf(var + 6.4e-4f);

    int c0 = warp * 64 + lane;
    float z0 = (a0 - mu) * inv * ln_g[c0] + ln_b[c0];
    float z1 = (a1 - mu) * inv * ln_g[c0 + 32] + ln_b[c0 + 32];
    z[base + lane]      = z0 * g[base + lane];
    z[base + 32 + lane] = z1 * g[base + 32 + lane];
}

// ---------------- launcher ----------------------------------------------------
extern "C" void kernel_launch(void* const* d_in, const int* in_sizes, int n_in,
                              void* d_out, int out_size)
{
    const float* x          = (const float*)d_in[0];
    const float* maa_x      = (const float*)d_in[1];
    const float* maa_w      = (const float*)d_in[2];
    const float* maa_k      = (const float*)d_in[3];
    const float* maa_v      = (const float*)d_in[4];
    const float* maa_r      = (const float*)d_in[5];
    const float* maa_g      = (const float*)d_in[6];
    const float* maa_w1     = (const float*)d_in[7];
    const float* maa_w2     = (const float*)d_in[8];
    const float* Wr         = (const float*)d_in[9];
    const float* Wk         = (const float*)d_in[10];
    const float* Wv         = (const float*)d_in[11];
    const float* Wo         = (const float*)d_in[12];
    const float* gate_w1    = (const float*)d_in[13];
    const float* gate_w2    = (const float*)d_in[14];
    const float* time_decay = (const float*)d_in[15];
    const float* decay_w1   = (const float*)d_in[16];
    const float* decay_w2   = (const float*)d_in[17];
    const float* u          = (const float*)d_in[18];
    const float* ln_g       = (const float*)d_in[19];
    const float* ln_b       = (const float*)d_in[20];
    (void)in_sizes; (void)n_in; (void)out_size;

    float *p_xx, *p_xxx, *p_xw, *p_xk, *p_xv, *p_xr, *p_xg;
    float *p_r, *p_k, *p_v, *p_w, *p_g, *p_y, *p_z, *p_lora, *p_small;
    float *p_D, *p_Sc, *p_rp, *p_pL;
    cudaGetSymbolAddress((void**)&p_xx, g_xx);
    cudaGetSymbolAddress((void**)&p_xxx, g_xxx);
    cudaGetSymbolAddress((void**)&p_xw, g_xw);
    cudaGetSymbolAddress((void**)&p_xk, g_xk);
    cudaGetSymbolAddress((void**)&p_xv, g_xv);
    cudaGetSymbolAddress((void**)&p_xr, g_xr);
    cudaGetSymbolAddress((void**)&p_xg, g_xg);
    cudaGetSymbolAddress((void**)&p_r, g_r);
    cudaGetSymbolAddress((void**)&p_k, g_k);
    cudaGetSymbolAddress((void**)&p_v, g_v);
    cudaGetSymbolAddress((void**)&p_w, g_w);
    cudaGetSymbolAddress((void**)&p_g, g_g);
    cudaGetSymbolAddress((void**)&p_y, g_y);
    cudaGetSymbolAddress((void**)&p_z, g_z);
    cudaGetSymbolAddress((void**)&p_lora, g_lora);
    cudaGetSymbolAddress((void**)&p_small, g_small);
    cudaGetSymbolAddress((void**)&p_D, g_D);
    cudaGetSymbolAddress((void**)&p_Sc, g_Sc);
    cudaGetSymbolAddress((void**)&p_rp, g_rp);
    cudaGetSymbolAddress((void**)&p_pL, g_pL);

    const long total = BTC;
    const int M = B_ * T_;          // 8192
    const int gy = M / BM;          // 64

    const int SMEM_A = (65 * 64 + 5 * 64 * STRD + 128) * 4;   // ~104 KB
    cudaFuncSetAttribute(wkv_chunkA, cudaFuncAttributeMaxDynamicSharedMemorySize, SMEM_A);

    // 1. time shift + maa_x mix
    shift_kernel<<<(int)((total + 255) / 256), 256>>>(x, maa_x, p_xx, p_xxx, total);

    // 2. lora = tanh(xxx @ maa_w1)
    gemm_k<1><<<dim3(2, gy), 256>>>(p_xxx, C_, maa_w1, 5 * DMIX,
                                    p_lora, 5 * DMIX, M, C_, 5 * DMIX, nullptr);

    // 3+4. fused mix GEMMs + token-shift blend
    mix5_fuse<<<dim3(M / 32, C_ / 128), 256>>>(p_lora, maa_w2, x, p_xx,
        maa_w, maa_k, maa_v, maa_r, maa_g,
        p_xw, p_xk, p_xv, p_xr, p_xg);

    // 5. r, k, v projections
    gemm_k<0><<<dim3(8, gy), 256>>>(p_xr, C_, Wr, C_, p_r, C_, M, C_, C_, nullptr);
    gemm_k<0><<<dim3(8, gy), 256>>>(p_xk, C_, Wk, C_, p_k, C_, M, C_, C_, nullptr);
    gemm_k<0><<<dim3(8, gy), 256>>>(p_xv, C_, Wv, C_, p_v, C_, M, C_, C_, nullptr);

    // 6. decay: lw = -exp(time_decay + tanh(xw@decay_w1)@decay_w2)
    gemm_k<1><<<dim3(1, gy), 256>>>(p_xw, C_, decay_w1, DDECAY,
                                    p_small, DDECAY, M, C_, DDECAY, nullptr);
    gemm_k<2><<<dim3(8, gy), 256>>>(p_small, DDECAY, decay_w2, C_,
                                    p_w, C_, M, DDECAY, C_, time_decay);

    // 7. chunked WKV6
    wkv_chunkA<<<NCHUNK, 256, SMEM_A>>>(p_r, p_k, p_v, p_w, u,
                                        p_y, p_D, p_rp, p_pL);
    wkv_chunkB<<<B_ * H_, 256>>>(p_D, p_pL, p_Sc);
    wkv_chunkC<<<NCHUNK, 256>>>(p_rp, p_Sc, p_y);

    // 8. gate
    gemm_k<1><<<dim3(1, gy), 256>>>(p_xg, C_, gate_w1, DGATE,
                                    p_small, DGATE, M, C_, DGATE, nullptr);
    gemm_k<0><<<dim3(8, gy), 256>>>(p_small, DGATE, gate_w2, C_,
                                    p_g, C_, M, DGATE, C_, nullptr);

    // 9. GroupNorm + gate multiply
    gn_kernel<<<M, 512>>>(p_y, ln_g, ln_b, p_g, p_z);

    // 10. out = z @ Wo
    gemm_k<0><<<dim3(8, gy), 256>>>(p_z, C_, Wo, C_, (float*)d_out, C_,
                                    M, C_, C_, nullptr);
}

// round 4
// speedup vs baseline: 2.3791x; 2.0012x over previous
#include <cuda_runtime.h>
#include <cuda_bf16.h>
#include <cstdint>
#include <math.h>

// Problem constants
#define B_  4
#define T_  2048
#define C_  1024
#define H_  16
#define N_  64
#define DMIX 32
#define DGATE 64
#define DDECAY 64

#define CHUNK 64
#define G_ 32                     // chunks per (b,h)
#define NCHUNK (B_*H_*G_)         // 2048
#define STRD 68                   // padded row stride for chunk smem tiles

static const long BTC = (long)B_ * T_ * C_;   // 8388608

// ---------------- scratch (device globals; no runtime allocation) -------------
__device__ float g_xx [ (long)B_*T_*C_ ];
__device__ float g_xxx[ (long)B_*T_*C_ ];
__device__ float g_xw [ (long)B_*T_*C_ ];
__device__ float g_xk [ (long)B_*T_*C_ ];
__device__ float g_xv [ (long)B_*T_*C_ ];
__device__ float g_xr [ (long)B_*T_*C_ ];
__device__ float g_xg [ (long)B_*T_*C_ ];
__device__ float g_r  [ (long)B_*T_*C_ ];
__device__ float g_k  [ (long)B_*T_*C_ ];
__device__ float g_v  [ (long)B_*T_*C_ ];
__device__ float g_w  [ (long)B_*T_*C_ ];   // stores lw = log(decay)
__device__ float g_g  [ (long)B_*T_*C_ ];
__device__ float g_y  [ (long)B_*T_*C_ ];
__device__ float g_z  [ (long)B_*T_*C_ ];
__device__ float g_lora [ (long)B_*T_*5*DMIX ];
__device__ float g_small[ (long)B_*T_*64 ];
__device__ float g_D  [ (long)NCHUNK*64*64 ];
__device__ float g_Sc [ (long)NCHUNK*64*64 ];
__device__ float g_rp [ (long)NCHUNK*64*64 ];
__device__ float g_pL [ (long)NCHUNK*64 ];
// transposed weights [N, K] K-major
__device__ float g_WrT[ (long)C_*C_ ];
__device__ float g_WkT[ (long)C_*C_ ];
__device__ float g_WvT[ (long)C_*C_ ];
__device__ float g_WoT[ (long)C_*C_ ];
__device__ float g_w1T[ (long)160*C_ ];
__device__ float g_dw1T[ (long)64*C_ ];
__device__ float g_gw1T[ (long)64*C_ ];
__device__ float g_dw2T[ (long)C_*64 ];
__device__ float g_gw2T[ (long)C_*64 ];

// ================= tf32 mma.sync GEMM ========================================
// C[M,N] = epi(A[M,K] @ Bt[N,K]^T).  BM=128, BN=128, BK=16.
// 256 threads = 8 warps in 2x4; warp tile 64x32; mma m16n8k8 tf32.
// EPI: 0 none, 1 tanh, 2 -exp(x + bias[col])
#define TSTR 20   // smem row stride (16 + 4 pad) -> conflict-free fragments

__device__ __forceinline__ uint32_t f2tf32(float f) {
    uint32_t o;
    asm("cvt.rna.tf32.f32 %0, %1;" : "=r"(o) : "f"(f));
    return o;
}
__device__ __forceinline__ void mma1688(float* d, const uint32_t* a, const uint32_t* b) {
    asm volatile(
        "mma.sync.aligned.m16n8k8.row.col.f32.tf32.tf32.f32 "
        "{%0,%1,%2,%3}, {%4,%5,%6,%7}, {%8,%9}, {%0,%1,%2,%3};"
        : "+f"(d[0]), "+f"(d[1]), "+f"(d[2]), "+f"(d[3])
        : "r"(a[0]), "r"(a[1]), "r"(a[2]), "r"(a[3]), "r"(b[0]), "r"(b[1]));
}

template<int EPI>
__global__ __launch_bounds__(256) void gemm_tc(
    const float* __restrict__ A, int lda,
    const float* __restrict__ Bt,           // [Nn_pad rows, K] K-major
    float* __restrict__ Cm, int ldc,
    int K, int Nn, const float* __restrict__ bias)
{
    __shared__ uint32_t As[2][128 * TSTR];
    __shared__ uint32_t Bs[2][128 * TSTR];

    const int tid = threadIdx.x;
    const int lane = tid & 31;
    const int wid = tid >> 5;
    const int wr = wid >> 2;            // 0..1
    const int wc = wid & 3;             // 0..3
    const int row0 = blockIdx.y * 128;
    const int col0 = blockIdx.x * 128;

    const int lr = tid >> 2;            // 0..63? no: 256 threads -> tid>>2 = 0..63
    // tile is 128 rows x 16 cols = 512 float4; 256 threads x 2
    float4 ra[2], rb[2];

    auto loadAB = [&](int kc) {
        const int k0 = kc * 16;
        #pragma unroll
        for (int l = 0; l < 2; l++) {
            int e = tid + (l << 8);
            int r = e >> 2, c = e & 3;
            ra[l] = *(const float4*)&A[(long)(row0 + r) * lda + k0 + (c << 2)];
            int br = col0 + r;
            if (br < Nn)
                rb[l] = *(const float4*)&Bt[(long)br * K + k0 + (c << 2)];
            else
                rb[l] = make_float4(0.f, 0.f, 0.f, 0.f);
        }
    };
    auto storeAB = [&](int buf) {
        #pragma unroll
        for (int l = 0; l < 2; l++) {
            int e = tid + (l << 8);
            int r = e >> 2, c = e & 3;
            uint32_t* ap = &As[buf][r * TSTR + (c << 2)];
            ap[0] = f2tf32(ra[l].x); ap[1] = f2tf32(ra[l].y);
            ap[2] = f2tf32(ra[l].z); ap[3] = f2tf32(ra[l].w);
            uint32_t* bp = &Bs[buf][r * TSTR + (c << 2)];
            bp[0] = f2tf32(rb[l].x); bp[1] = f2tf32(rb[l].y);
            bp[2] = f2tf32(rb[l].z); bp[3] = f2tf32(rb[l].w);
        }
    };

    float acc[4][4][4];
    #pragma unroll
    for (int mi = 0; mi < 4; mi++)
        #pragma unroll
        for (int ni = 0; ni < 4; ni++)
            #pragma unroll
            for (int e = 0; e < 4; e++) acc[mi][ni][e] = 0.f;

    const int NKT = K >> 4;
    loadAB(0);
    storeAB(0);
    __syncthreads();

    const int lg = lane >> 2;          // group id 0..7
    const int lt = lane & 3;           // thread-in-group

    for (int kc = 0; kc < NKT; kc++) {
        const int cur = kc & 1;
        if (kc + 1 < NKT) loadAB(kc + 1);

        #pragma unroll
        for (int ks = 0; ks < 2; ks++) {
            const int k0 = (ks << 3) + lt;
            uint32_t af[4][4], bf[4][2];
            #pragma unroll
            for (int mi = 0; mi < 4; mi++) {
                int rm = wr * 64 + mi * 16 + lg;
                af[mi][0] = As[cur][rm * TSTR + k0];
                af[mi][1] = As[cur][(rm + 8) * TSTR + k0];
                af[mi][2] = As[cur][rm * TSTR + k0 + 4];
                af[mi][3] = As[cur][(rm + 8) * TSTR + k0 + 4];
            }
            #pragma unroll
            for (int ni = 0; ni < 4; ni++) {
                int cn = wc * 32 + ni * 8 + lg;
                bf[ni][0] = Bs[cur][cn * TSTR + k0];
                bf[ni][1] = Bs[cur][cn * TSTR + k0 + 4];
            }
            #pragma unroll
            for (int mi = 0; mi < 4; mi++)
                #pragma unroll
                for (int ni = 0; ni < 4; ni++)
                    mma1688(acc[mi][ni], af[mi], bf[ni]);
        }

        if (kc + 1 < NKT) storeAB(cur ^ 1);
        __syncthreads();
    }

    // epilogue
    #pragma unroll
    for (int mi = 0; mi < 4; mi++) {
        int gr0 = row0 + wr * 64 + mi * 16 + lg;
        #pragma unroll
        for (int ni = 0; ni < 4; ni++) {
            int gc = col0 + wc * 32 + ni * 8 + 2 * lt;
            if (gc < Nn) {
                float v0 = acc[mi][ni][0], v1 = acc[mi][ni][1];
                float v2 = acc[mi][ni][2], v3 = acc[mi][ni][3];
                if (EPI == 1) {
                    v0 = tanhf(v0); v1 = tanhf(v1); v2 = tanhf(v2); v3 = tanhf(v3);
                } else if (EPI == 2) {
                    float b0 = bias[gc], b1 = bias[gc + 1];
                    v0 = -expf(v0 + b0); v1 = -expf(v1 + b1);
                    v2 = -expf(v2 + b0); v3 = -expf(v3 + b1);
                }
                *(float2*)&Cm[(long)gr0 * ldc + gc] = make_float2(v0, v1);
                *(float2*)&Cm[(long)(gr0 + 8) * ldc + gc] = make_float2(v2, v3);
            }
        }
    }
}

// ---------------- weight transpose: dst[n*R + r] = src[r*Ncol + n] -----------
__global__ __launch_bounds__(256) void transpose_k(
    const float* __restrict__ src, float* __restrict__ dst, int R, int Ncol)
{
    __shared__ float t[32][33];
    const int bx = blockIdx.x * 32, by = blockIdx.y * 32;
    const int x = threadIdx.x, y = threadIdx.y;
    #pragma unroll
    for (int i = 0; i < 32; i += 8) {
        int r = by + y + i, n = bx + x;
        if (r < R && n < Ncol) t[y + i][x] = src[(long)r * Ncol + n];
    }
    __syncthreads();
    #pragma unroll
    for (int i = 0; i < 32; i += 8) {
        int n = bx + y + i, r = by + x;
        if (n < Ncol && r < R) dst[(long)n * R + r] = t[x][y + i];
    }
}

// ---------------- elementwise: time shift + maa_x mix ------------------------
__global__ void shift_kernel(const float* __restrict__ x,
                             const float* __restrict__ maa_x,
                             float* __restrict__ xx, float* __restrict__ xxx,
                             long total)
{
    long idx = (long)blockIdx.x * blockDim.x + threadIdx.x;
    if (idx >= total) return;
    int c = (int)(idx % C_);
    long rt = idx / C_;
    int t = (int)(rt % T_);
    float xv = x[idx];
    float xp = (t > 0) ? x[idx - C_] : 0.f;
    float d = xp - xv;
    xx[idx] = d;
    xxx[idx] = xv + d * maa_x[c];
}

// ---------------- fused: m_f = lora_f @ w2_f; x_f = x + xx*(maa_f + m_f) -----
__global__ __launch_bounds__(256) void mix5_fuse(
    const float* __restrict__ lora,
    const float* __restrict__ w2,
    const float* __restrict__ x, const float* __restrict__ xx,
    const float* __restrict__ maa_w, const float* __restrict__ maa_k,
    const float* __restrict__ maa_v, const float* __restrict__ maa_r,
    const float* __restrict__ maa_g,
    float* __restrict__ xw, float* __restrict__ xk, float* __restrict__ xv_,
    float* __restrict__ xr, float* __restrict__ xg)
{
    __shared__ float ls[32 * 160];
    __shared__ float ws[32 * 128];
    const int tid = threadIdx.x;
    const int rb = blockIdx.x * 32;
    const int cb = blockIdx.y * 128;

    for (int e = tid; e < 32 * 160; e += 256)
        ls[e] = lora[(long)(rb + e / 160) * 160 + (e % 160)];

    const int r = tid >> 3;
    const int j0 = (tid & 7) * 16;
    const long gbase = (long)(rb + r) * C_ + cb + j0;
    float xvv[16], xxv[16];
    #pragma unroll
    for (int jj = 0; jj < 16; jj += 4) {
        *(float4*)&xvv[jj] = *(const float4*)&x[gbase + jj];
        *(float4*)&xxv[jj] = *(const float4*)&xx[gbase + jj];
    }
    const float* maas[5] = { maa_w, maa_k, maa_v, maa_r, maa_g };
    float* outs[5] = { xw, xk, xv_, xr, xg };
    #pragma unroll
    for (int f = 0; f < 5; f++) {
        __syncthreads();
        for (int e = tid; e < 32 * 128; e += 256)
            ws[e] = w2[((long)f * 32 + e / 128) * 1024 + cb + (e & 127)];
        __syncthreads();
        float acc[16];
        #pragma unroll
        for (int jj = 0; jj < 16; jj++) acc[jj] = 0.f;
        #pragma unroll 8
        for (int d = 0; d < 32; d++) {
            float lv = ls[r * 160 + f * 32 + d];
            #pragma unroll
            for (int jj = 0; jj < 16; jj++)
                acc[jj] = fmaf(lv, ws[d * 128 + j0 + jj], acc[jj]);
        }
        const float* ma = maas[f];
        float* outp = outs[f];
        #pragma unroll
        for (int jj = 0; jj < 16; jj++) {
            float mm = ma[cb + j0 + jj] + acc[jj];
            acc[jj] = fmaf(xxv[jj], mm, xvv[jj]);
        }
        #pragma unroll
        for (int jj = 0; jj < 16; jj += 4)
            *(float4*)&outp[gbase + jj] = *(float4*)&acc[jj];
    }
}

// ---------------- chunked WKV6 -----------------------------------------------
__global__ __launch_bounds__(256) void wkv_chunkA(
    const float* __restrict__ r, const float* __restrict__ k,
    const float* __restrict__ v, const float* __restrict__ lw,
    const float* __restrict__ u,
    float* __restrict__ y, float* __restrict__ Dout,
    float* __restrict__ rpout, float* __restrict__ pLout)
{
    extern __shared__ float sm[];
    float* lp   = sm;
    float* bufA = lp + 65 * 64;
    float* rpT  = bufA + 64 * STRD;
    float* kpT  = rpT + 64 * STRD;
    float* kpp  = kpT + 64 * STRD;
    float* vsm  = kpp + 64 * STRD;
    float* dsm  = vsm + 64 * STRD;
    float* usm  = dsm + 64;

    const int tid = threadIdx.x;
    const int chunk = blockIdx.x;
    const int bh = chunk >> 5;
    const int c  = chunk & 31;
    const int b = bh >> 4, h = bh & 15;
    const long base = ((long)b * T_ + c * CHUNK) * C_ + h * 64;

    if (tid < 64) usm[tid] = u[h * 64 + tid];
    const int i  = tid & 63;
    const int tq = tid >> 6;

    #pragma unroll
    for (int e = 0; e < 16; e++) {
        int t = tq + 4 * e;
        bufA[t * STRD + i] = lw[base + (long)t * C_ + i];
    }
    __syncthreads();

    if (tid < 64) {
        float run = 0.f;
        for (int t = 0; t < 64; t++) {
            lp[t * 64 + tid] = run;
            run += bufA[t * STRD + tid];
        }
        lp[64 * 64 + tid] = run;
        pLout[(long)chunk * 64 + tid] = run;
    }
    __syncthreads();

    #pragma unroll
    for (int e = 0; e < 16; e++) {
        int t = tq + 4 * e;
        long gi = base + (long)t * C_ + i;
        float rr = r[gi], kk = k[gi];
        float lpti = lp[t * 64 + i];
        float lpn  = lpti + bufA[t * STRD + i];
        float lpL  = lp[64 * 64 + i];
        rpT[i * STRD + t] = rr * __expf(lpti);
        kpT[i * STRD + t] = kk * __expf(-lpn);
        kpp[t * STRD + i] = kk * __expf(lpL - lpn);
        vsm[t * STRD + i] = v[gi];
    }
    {
        int t = tid >> 2, q = tid & 3;
        long gb = base + (long)t * C_;
        float p = 0.f;
        #pragma unroll
        for (int ii = 0; ii < 16; ii++) {
            int ci = q * 16 + ii;
            p += r[gb + ci] * usm[ci] * k[gb + ci];
        }
        p += __shfl_xor_sync(0xffffffffu, p, 1);
        p += __shfl_xor_sync(0xffffffffu, p, 2);
        if (q == 0) dsm[t] = p;
    }
    __syncthreads();

    {
        float* rpg = rpout + (long)chunk * 64 * 64;
        #pragma unroll
        for (int e = 0; e < 16; e++) {
            int flat = tid + 256 * e;
            rpg[flat] = rpT[(flat >> 6) * STRD + (flat & 63)];
        }
    }

    {
        int t0 = (tid >> 4) * 4, s0 = (tid & 15) * 4;
        float acc[4][4];
        #pragma unroll
        for (int a = 0; a < 4; a++)
            #pragma unroll
            for (int bq = 0; bq < 4; bq++) acc[a][bq] = 0.f;
        for (int ii = 0; ii < 64; ii++) {
            float4 a4 = *(const float4*)&rpT[ii * STRD + t0];
            float4 b4 = *(const float4*)&kpT[ii * STRD + s0];
            float av[4] = { a4.x, a4.y, a4.z, a4.w };
            float bv[4] = { b4.x, b4.y, b4.z, b4.w };
            #pragma unroll
            for (int a = 0; a < 4; a++)
                #pragma unroll
                for (int bq = 0; bq < 4; bq++)
                    acc[a][bq] = fmaf(av[a], bv[bq], acc[a][bq]);
        }
        __syncthreads();
        #pragma unroll
        for (int a = 0; a < 4; a++)
            #pragma unroll
            for (int bq = 0; bq < 4; bq++) {
                int tt = t0 + a, ss = s0 + bq;
                float val = (tt > ss) ? acc[a][bq] : ((tt == ss) ? dsm[tt] : 0.f);
                bufA[ss * STRD + tt] = val;
            }
    }
    __syncthreads();

    {
        int t0 = (tid >> 4) * 4, j0 = (tid & 15) * 4;
        float acc[4][4];
        #pragma unroll
        for (int a = 0; a < 4; a++)
            #pragma unroll
            for (int bq = 0; bq < 4; bq++) acc[a][bq] = 0.f;
        for (int s = 0; s < 64; s++) {
            float4 a4 = *(const float4*)&bufA[s * STRD + t0];
            float4 b4 = *(const float4*)&vsm[s * STRD + j0];
            float av[4] = { a4.x, a4.y, a4.z, a4.w };
            float bv[4] = { b4.x, b4.y, b4.z, b4.w };
            #pragma unroll
            for (int a = 0; a < 4; a++)
                #pragma unroll
                for (int bq = 0; bq < 4; bq++)
                    acc[a][bq] = fmaf(av[a], bv[bq], acc[a][bq]);
        }
        #pragma unroll
        for (int a = 0; a < 4; a++) {
            float4 o = make_float4(acc[a][0], acc[a][1], acc[a][2], acc[a][3]);
            *(float4*)&y[base + (long)(t0 + a) * C_ + j0] = o;
        }
    }

    {
        int i0 = (tid >> 4) * 4, j0 = (tid & 15) * 4;
        float acc[4][4];
        #pragma unroll
        for (int a = 0; a < 4; a++)
            #pragma unroll
            for (int bq = 0; bq < 4; bq++) acc[a][bq] = 0.f;
        for (int s = 0; s < 64; s++) {
            float4 a4 = *(const float4*)&kpp[s * STRD + i0];
            float4 b4 = *(const float4*)&vsm[s * STRD + j0];
            float av[4] = { a4.x, a4.y, a4.z, a4.w };
            float bv[4] = { b4.x, b4.y, b4.z, b4.w };
            #pragma unroll
            for (int a = 0; a < 4; a++)
                #pragma unroll
                for (int bq = 0; bq < 4; bq++)
                    acc[a][bq] = fmaf(av[a], bv[bq], acc[a][bq]);
        }
        float* Dp = Dout + (long)chunk * 4096;
        #pragma unroll
        for (int a = 0; a < 4; a++) {
            float4 o = make_float4(acc[a][0], acc[a][1], acc[a][2], acc[a][3]);
            *(float4*)&Dp[(i0 + a) * 64 + j0] = o;
        }
    }
}

__global__ __launch_bounds__(256) void wkv_chunkB(
    const float* __restrict__ D, const float* __restrict__ pL,
    float* __restrict__ S)
{
    const int bh = blockIdx.x;
    const int tid = threadIdx.x;
    const int i = tid >> 2;
    const int jb = (tid & 3) * 16;
    float4 s0 = {0,0,0,0}, s1 = {0,0,0,0}, s2 = {0,0,0,0}, s3 = {0,0,0,0};
    for (int c = 0; c < G_; c++) {
        long chunk = (long)bh * G_ + c;
        long off = chunk * 4096 + i * 64 + jb;
        *(float4*)&S[off + 0]  = s0;
        *(float4*)&S[off + 4]  = s1;
        *(float4*)&S[off + 8]  = s2;
        *(float4*)&S[off + 12] = s3;
        float pl = __expf(pL[chunk * 64 + i]);
        float4 d0 = *(const float4*)&D[off + 0];
        float4 d1 = *(const float4*)&D[off + 4];
        float4 d2 = *(const float4*)&D[off + 8];
        float4 d3 = *(const float4*)&D[off + 12];
        s0 = make_float4(fmaf(pl, s0.x, d0.x), fmaf(pl, s0.y, d0.y), fmaf(pl, s0.z, d0.z), fmaf(pl, s0.w, d0.w));
        s1 = make_float4(fmaf(pl, s1.x, d1.x), fmaf(pl, s1.y, d1.y), fmaf(pl, s1.z, d1.z), fmaf(pl, s1.w, d1.w));
        s2 = make_float4(fmaf(pl, s2.x, d2.x), fmaf(pl, s2.y, d2.y), fmaf(pl, s2.z, d2.z), fmaf(pl, s2.w, d2.w));
        s3 = make_float4(fmaf(pl, s3.x, d3.x), fmaf(pl, s3.y, d3.y), fmaf(pl, s3.z, d3.z), fmaf(pl, s3.w, d3.w));
    }
}

__global__ __launch_bounds__(256) void wkv_chunkC(
    const float* __restrict__ rp, const float* __restrict__ S,
    float* __restrict__ y)
{
    __shared__ float rps[64 * 64];
    __shared__ float Ss[64 * 64];
    const int tid = threadIdx.x;
    const int chunk = blockIdx.x;
    const int bh = chunk >> 5;
    const int c  = chunk & 31;
    const int b = bh >> 4, h = bh & 15;
    const long base = ((long)b * T_ + c * CHUNK) * C_ + h * 64;

    const float* rpg = rp + (long)chunk * 4096;
    const float* Sg  = S  + (long)chunk * 4096;
    #pragma unroll
    for (int e = 0; e < 4; e++) {
        int f4 = tid + 256 * e;
        *(float4*)&rps[f4 * 4] = *(const float4*)&rpg[f4 * 4];
        *(float4*)&Ss[f4 * 4]  = *(const float4*)&Sg[f4 * 4];
    }
    __syncthreads();

    int t0 = (tid >> 4) * 4, j0 = (tid & 15) * 4;
    float acc[4][4];
    #pragma unroll
    for (int a = 0; a < 4; a++)
        #pragma unroll
        for (int bq = 0; bq < 4; bq++) acc[a][bq] = 0.f;
    for (int ii = 0; ii < 64; ii++) {
        float4 a4 = *(const float4*)&rps[ii * 64 + t0];
        float4 b4 = *(const float4*)&Ss[ii * 64 + j0];
        float av[4] = { a4.x, a4.y, a4.z, a4.w };
        float bv[4] = { b4.x, b4.y, b4.z, b4.w };
        #pragma unroll
        for (int a = 0; a < 4; a++)
            #pragma unroll
            for (int bq = 0; bq < 4; bq++)
                acc[a][bq] = fmaf(av[a], bv[bq], acc[a][bq]);
    }
    #pragma unroll
    for (int a = 0; a < 4; a++) {
        long yo = base + (long)(t0 + a) * C_ + j0;
        float4 cur = *(const float4*)&y[yo];
        cur.x += acc[a][0]; cur.y += acc[a][1];
        cur.z += acc[a][2]; cur.w += acc[a][3];
        *(float4*)&y[yo] = cur;
    }
}

// ---------------- GroupNorm over heads + gate multiply -----------------------
__global__ __launch_bounds__(512) void gn_kernel(
    const float* __restrict__ y, const float* __restrict__ ln_g,
    const float* __restrict__ ln_b, const float* __restrict__ g,
    float* __restrict__ z)
{
    const int bt = blockIdx.x;
    const int warp = threadIdx.x >> 5;
    const int lane = threadIdx.x & 31;
    const long base = (long)bt * C_ + warp * 64;

    float a0 = y[base + lane];
    float a1 = y[base + 32 + lane];
    float sum = a0 + a1;
    float sq = a0 * a0 + a1 * a1;
    #pragma unroll
    for (int off = 16; off > 0; off >>= 1) {
        sum += __shfl_xor_sync(0xffffffffu, sum, off);
        sq  += __shfl_xor_sync(0xffffffffu, sq,  off);
    }
    float mu = sum * (1.f / 64.f);
    float var = sq * (1.f / 64.f) - mu * mu;
    float inv = rsqrtf(var + 6.4e-4f);

    int c0 = warp * 64 + lane;
    float z0 = (a0 - mu) * inv * ln_g[c0] + ln_b[c0];
    float z1 = (a1 - mu) * inv * ln_g[c0 + 32] + ln_b[c0 + 32];
    z[base + lane]      = z0 * g[base + lane];
    z[base + 32 + lane] = z1 * g[base + 32 + lane];
}

// ---------------- launcher ----------------------------------------------------
extern "C" void kernel_launch(void* const* d_in, const int* in_sizes, int n_in,
                              void* d_out, int out_size)
{
    const float* x          = (const float*)d_in[0];
    const float* maa_x      = (const float*)d_in[1];
    const float* maa_w      = (const float*)d_in[2];
    const float* maa_k      = (const float*)d_in[3];
    const float* maa_v      = (const float*)d_in[4];
    const float* maa_r      = (const float*)d_in[5];
    const float* maa_g      = (const float*)d_in[6];
    const float* maa_w1     = (const float*)d_in[7];
    const float* maa_w2     = (const float*)d_in[8];
    const float* Wr         = (const float*)d_in[9];
    const float* Wk         = (const float*)d_in[10];
    const float* Wv         = (const float*)d_in[11];
    const float* Wo         = (const float*)d_in[12];
    const float* gate_w1    = (const float*)d_in[13];
    const float* gate_w2    = (const float*)d_in[14];
    const float* time_decay = (const float*)d_in[15];
    const float* decay_w1   = (const float*)d_in[16];
    const float* decay_w2   = (const float*)d_in[17];
    const float* u          = (const float*)d_in[18];
    const float* ln_g       = (const float*)d_in[19];
    const float* ln_b       = (const float*)d_in[20];
    (void)in_sizes; (void)n_in; (void)out_size;

    float *p_xx, *p_xxx, *p_xw, *p_xk, *p_xv, *p_xr, *p_xg;
    float *p_r, *p_k, *p_v, *p_w, *p_g, *p_y, *p_z, *p_lora, *p_small;
    float *p_D, *p_Sc, *p_rp, *p_pL;
    float *p_WrT, *p_WkT, *p_WvT, *p_WoT, *p_w1T, *p_dw1T, *p_gw1T, *p_dw2T, *p_gw2T;
    cudaGetSymbolAddress((void**)&p_xx, g_xx);
    cudaGetSymbolAddress((void**)&p_xxx, g_xxx);
    cudaGetSymbolAddress((void**)&p_xw, g_xw);
    cudaGetSymbolAddress((void**)&p_xk, g_xk);
    cudaGetSymbolAddress((void**)&p_xv, g_xv);
    cudaGetSymbolAddress((void**)&p_xr, g_xr);
    cudaGetSymbolAddress((void**)&p_xg, g_xg);
    cudaGetSymbolAddress((void**)&p_r, g_r);
    cudaGetSymbolAddress((void**)&p_k, g_k);
    cudaGetSymbolAddress((void**)&p_v, g_v);
    cudaGetSymbolAddress((void**)&p_w, g_w);
    cudaGetSymbolAddress((void**)&p_g, g_g);
    cudaGetSymbolAddress((void**)&p_y, g_y);
    cudaGetSymbolAddress((void**)&p_z, g_z);
    cudaGetSymbolAddress((void**)&p_lora, g_lora);
    cudaGetSymbolAddress((void**)&p_small, g_small);
    cudaGetSymbolAddress((void**)&p_D, g_D);
    cudaGetSymbolAddress((void**)&p_Sc, g_Sc);
    cudaGetSymbolAddress((void**)&p_rp, g_rp);
    cudaGetSymbolAddress((void**)&p_pL, g_pL);
    cudaGetSymbolAddress((void**)&p_WrT, g_WrT);
    cudaGetSymbolAddress((void**)&p_WkT, g_WkT);
    cudaGetSymbolAddress((void**)&p_WvT, g_WvT);
    cudaGetSymbolAddress((void**)&p_WoT, g_WoT);
    cudaGetSymbolAddress((void**)&p_w1T, g_w1T);
    cudaGetSymbolAddress((void**)&p_dw1T, g_dw1T);
    cudaGetSymbolAddress((void**)&p_gw1T, g_gw1T);
    cudaGetSymbolAddress((void**)&p_dw2T, g_dw2T);
    cudaGetSymbolAddress((void**)&p_gw2T, g_gw2T);

    const long total = BTC;
    const int M = B_ * T_;          // 8192
    const int gy = M / 128;         // 64

    const int SMEM_A = (65 * 64 + 5 * 64 * STRD + 128) * 4;
    cudaFuncSetAttribute(wkv_chunkA, cudaFuncAttributeMaxDynamicSharedMemorySize, SMEM_A);

    // 0. transpose weights to [N,K] K-major
    transpose_k<<<dim3(32, 32), dim3(32, 8)>>>(Wr, p_WrT, C_, C_);
    transpose_k<<<dim3(32, 32), dim3(32, 8)>>>(Wk, p_WkT, C_, C_);
    transpose_k<<<dim3(32, 32), dim3(32, 8)>>>(Wv, p_WvT, C_, C_);
    transpose_k<<<dim3(32, 32), dim3(32, 8)>>>(Wo, p_WoT, C_, C_);
    transpose_k<<<dim3(5, 32), dim3(32, 8)>>>(maa_w1, p_w1T, C_, 160);
    transpose_k<<<dim3(2, 32), dim3(32, 8)>>>(decay_w1, p_dw1T, C_, 64);
    transpose_k<<<dim3(2, 32), dim3(32, 8)>>>(gate_w1,  p_gw1T, C_, 64);
    transpose_k<<<dim3(32, 2), dim3(32, 8)>>>(decay_w2, p_dw2T, 64, C_);
    transpose_k<<<dim3(32, 2), dim3(32, 8)>>>(gate_w2,  p_gw2T, 64, C_);

    // 1. time shift + maa_x mix
    shift_kernel<<<(int)((total + 255) / 256), 256>>>(x, maa_x, p_xx, p_xxx, total);

    // 2. lora = tanh(xxx @ maa_w1)   N=160 (guarded)
    gemm_tc<1><<<dim3(2, gy), 256>>>(p_xxx, C_, p_w1T, p_lora, 160, C_, 160, nullptr);

    // 3+4. fused mix GEMMs + token-shift blend
    mix5_fuse<<<dim3(M / 32, C_ / 128), 256>>>(p_lora, maa_w2, x, p_xx,
        maa_w, maa_k, maa_v, maa_r, maa_g,
        p_xw, p_xk, p_xv, p_xr, p_xg);

    // 5. r, k, v projections (tf32 mma.sync)
    gemm_tc<0><<<dim3(8, gy), 256>>>(p_xr, C_, p_WrT, p_r, C_, C_, C_, nullptr);
    gemm_tc<0><<<dim3(8, gy), 256>>>(p_xk, C_, p_WkT, p_k, C_, C_, C_, nullptr);
    gemm_tc<0><<<dim3(8, gy), 256>>>(p_xv, C_, p_WvT, p_v, C_, C_, C_, nullptr);

    // 6. decay: lw = -exp(time_decay + tanh(xw@decay_w1)@decay_w2)
    gemm_tc<1><<<dim3(1, gy), 256>>>(p_xw, C_, p_dw1T, p_small, 64, C_, 64, nullptr);
    gemm_tc<2><<<dim3(8, gy), 256>>>(p_small, 64, p_dw2T, p_w, C_, 64, C_, time_decay);

    // 7. chunked WKV6
    wkv_chunkA<<<NCHUNK, 256, SMEM_A>>>(p_r, p_k, p_v, p_w, u,
                                        p_y, p_D, p_rp, p_pL);
    wkv_chunkB<<<B_ * H_, 256>>>(p_D, p_pL, p_Sc);
    wkv_chunkC<<<NCHUNK, 256>>>(p_rp, p_Sc, p_y);

    // 8. gate
    gemm_tc<1><<<dim3(1, gy), 256>>>(p_xg, C_, p_gw1T, p_small, 64, C_, 64, nullptr);
    gemm_tc<0><<<dim3(8, gy), 256>>>(p_small, 64, p_gw2T, p_g, C_, 64, C_, nullptr);

    // 9. GroupNorm + gate multiply
    gn_kernel<<<M, 512>>>(p_y, ln_g, ln_b, p_g, p_z);

    // 10. out = z @ Wo
    gemm_tc<0><<<dim3(8, gy), 256>>>(p_z, C_, p_WoT, (float*)d_out, C_, C_, C_, nullptr);
}

// round 5
// speedup vs baseline: 2.4222x; 1.0181x over previous
#include <cuda_runtime.h>
#include <cuda_bf16.h>
#include <cstdint>
#include <math.h>

// Problem constants
#define B_  4
#define T_  2048
#define C_  1024
#define H_  16
#define N_  64
#define DMIX 32
#define DGATE 64
#define DDECAY 64

#define CHUNK 64
#define G_ 32                     // chunks per (b,h)
#define NCHUNK (B_*H_*G_)         // 2048
#define STRD 68                   // padded row stride for chunk smem tiles

static const long BTC = (long)B_ * T_ * C_;   // 8388608

// ---------------- scratch (device globals; no runtime allocation) -------------
__device__ float g_xx [ (long)B_*T_*C_ ];
__device__ float g_xxx[ (long)B_*T_*C_ ];
__device__ float g_xw [ (long)B_*T_*C_ ];
__device__ float g_xk [ (long)B_*T_*C_ ];
__device__ float g_xv [ (long)B_*T_*C_ ];
__device__ float g_xr [ (long)B_*T_*C_ ];
__device__ float g_xg [ (long)B_*T_*C_ ];
__device__ float g_r  [ (long)B_*T_*C_ ];
__device__ float g_k  [ (long)B_*T_*C_ ];
__device__ float g_v  [ (long)B_*T_*C_ ];
__device__ float g_w  [ (long)B_*T_*C_ ];   // stores lw = log(decay)
__device__ float g_g  [ (long)B_*T_*C_ ];
__device__ float g_y  [ (long)B_*T_*C_ ];
__device__ float g_z  [ (long)B_*T_*C_ ];
__device__ float g_lora [ (long)B_*T_*5*DMIX ];
__device__ float g_small[ (long)B_*T_*64 ];
__device__ float g_D  [ (long)NCHUNK*64*64 ];
__device__ float g_Sc [ (long)NCHUNK*64*64 ];
__device__ float g_rp [ (long)NCHUNK*64*64 ];
__device__ float g_pL [ (long)NCHUNK*64 ];
// transposed weights [N, K] K-major
__device__ float g_WrT[ (long)C_*C_ ];
__device__ float g_WkT[ (long)C_*C_ ];
__device__ float g_WvT[ (long)C_*C_ ];
__device__ float g_WoT[ (long)C_*C_ ];
__device__ float g_w1T[ (long)160*C_ ];
__device__ float g_dw1T[ (long)64*C_ ];
__device__ float g_gw1T[ (long)64*C_ ];
__device__ float g_dw2T[ (long)C_*64 ];
__device__ float g_gw2T[ (long)C_*64 ];

// ================= tf32 mma.sync GEMM ========================================
#define TSTR 20   // smem row stride (16 + 4 pad) -> conflict-free fragments

__device__ __forceinline__ uint32_t f2tf32(float f) {
    uint32_t o;
    asm("cvt.rna.tf32.f32 %0, %1;" : "=r"(o) : "f"(f));
    return o;
}
__device__ __forceinline__ void mma1688(float* d, const uint32_t* a, const uint32_t* b) {
    asm volatile(
        "mma.sync.aligned.m16n8k8.row.col.f32.tf32.tf32.f32 "
        "{%0,%1,%2,%3}, {%4,%5,%6,%7}, {%8,%9}, {%0,%1,%2,%3};"
        : "+f"(d[0]), "+f"(d[1]), "+f"(d[2]), "+f"(d[3])
        : "r"(a[0]), "r"(a[1]), "r"(a[2]), "r"(a[3]), "r"(b[0]), "r"(b[1]));
}

// ---- big tile: BM=128, BN=128, BK=16, 256 threads (8 warps 2x4, warp 64x32) --
// EPI: 0 none, 1 tanh, 2 -exp(x + bias[col])
template<int EPI>
__global__ __launch_bounds__(256) void gemm_tc(
    const float* __restrict__ A, int lda,
    const float* __restrict__ Bt,           // [Nn rows, K] K-major
    float* __restrict__ Cm, int ldc,
    int K, int Nn, const float* __restrict__ bias)
{
    __shared__ uint32_t As[2][128 * TSTR];
    __shared__ uint32_t Bs[2][128 * TSTR];

    const int tid = threadIdx.x;
    const int lane = tid & 31;
    const int wid = tid >> 5;
    const int wr = wid >> 2;
    const int wc = wid & 3;
    const int row0 = blockIdx.y * 128;
    const int col0 = blockIdx.x * 128;

    float4 ra[2], rb[2];

    auto loadAB = [&](int kc) {
        const int k0 = kc * 16;
        #pragma unroll
        for (int l = 0; l < 2; l++) {
            int e = tid + (l << 8);
            int r = e >> 2, c = e & 3;
            ra[l] = *(const float4*)&A[(long)(row0 + r) * lda + k0 + (c << 2)];
            int br = col0 + r;
            if (br < Nn)
                rb[l] = *(const float4*)&Bt[(long)br * K + k0 + (c << 2)];
            else
                rb[l] = make_float4(0.f, 0.f, 0.f, 0.f);
        }
    };
    auto storeAB = [&](int buf) {
        #pragma unroll
        for (int l = 0; l < 2; l++) {
            int e = tid + (l << 8);
            int r = e >> 2, c = e & 3;
            uint32_t* ap = &As[buf][r * TSTR + (c << 2)];
            ap[0] = f2tf32(ra[l].x); ap[1] = f2tf32(ra[l].y);
            ap[2] = f2tf32(ra[l].z); ap[3] = f2tf32(ra[l].w);
            uint32_t* bp = &Bs[buf][r * TSTR + (c << 2)];
            bp[0] = f2tf32(rb[l].x); bp[1] = f2tf32(rb[l].y);
            bp[2] = f2tf32(rb[l].z); bp[3] = f2tf32(rb[l].w);
        }
    };

    float acc[4][4][4];
    #pragma unroll
    for (int mi = 0; mi < 4; mi++)
        #pragma unroll
        for (int ni = 0; ni < 4; ni++)
            #pragma unroll
            for (int e = 0; e < 4; e++) acc[mi][ni][e] = 0.f;

    const int NKT = K >> 4;
    loadAB(0);
    storeAB(0);
    __syncthreads();

    const int lg = lane >> 2;
    const int lt = lane & 3;

    for (int kc = 0; kc < NKT; kc++) {
        const int cur = kc & 1;
        if (kc + 1 < NKT) loadAB(kc + 1);

        #pragma unroll
        for (int ks = 0; ks < 2; ks++) {
            const int k0 = (ks << 3) + lt;
            uint32_t af[4][4], bf[4][2];
            #pragma unroll
            for (int mi = 0; mi < 4; mi++) {
                int rm = wr * 64 + mi * 16 + lg;
                af[mi][0] = As[cur][rm * TSTR + k0];
                af[mi][1] = As[cur][(rm + 8) * TSTR + k0];
                af[mi][2] = As[cur][rm * TSTR + k0 + 4];
                af[mi][3] = As[cur][(rm + 8) * TSTR + k0 + 4];
            }
            #pragma unroll
            for (int ni = 0; ni < 4; ni++) {
                int cn = wc * 32 + ni * 8 + lg;
                bf[ni][0] = Bs[cur][cn * TSTR + k0];
                bf[ni][1] = Bs[cur][cn * TSTR + k0 + 4];
            }
            #pragma unroll
            for (int mi = 0; mi < 4; mi++)
                #pragma unroll
                for (int ni = 0; ni < 4; ni++)
                    mma1688(acc[mi][ni], af[mi], bf[ni]);
        }

        if (kc + 1 < NKT) storeAB(cur ^ 1);
        __syncthreads();
    }

    #pragma unroll
    for (int mi = 0; mi < 4; mi++) {
        int gr0 = row0 + wr * 64 + mi * 16 + lg;
        #pragma unroll
        for (int ni = 0; ni < 4; ni++) {
            int gc = col0 + wc * 32 + ni * 8 + 2 * lt;
            if (gc < Nn) {
                float v0 = acc[mi][ni][0], v1 = acc[mi][ni][1];
                float v2 = acc[mi][ni][2], v3 = acc[mi][ni][3];
                if (EPI == 1) {
                    v0 = tanhf(v0); v1 = tanhf(v1); v2 = tanhf(v2); v3 = tanhf(v3);
                } else if (EPI == 2) {
                    float b0 = bias[gc], b1 = bias[gc + 1];
                    v0 = -expf(v0 + b0); v1 = -expf(v1 + b1);
                    v2 = -expf(v2 + b0); v3 = -expf(v3 + b1);
                }
                *(float2*)&Cm[(long)gr0 * ldc + gc] = make_float2(v0, v1);
                *(float2*)&Cm[(long)(gr0 + 8) * ldc + gc] = make_float2(v2, v3);
            }
        }
    }
}

// ---- small tile: BM=64, BN=64, BK=16, 128 threads (4 warps 2x2, warp 32x32) --
template<int EPI>
__global__ __launch_bounds__(128) void gemm_tc64(
    const float* __restrict__ A, int lda,
    const float* __restrict__ Bt,           // [Nn rows, K] K-major
    float* __restrict__ Cm, int ldc,
    int K, int Nn, const float* __restrict__ bias)
{
    __shared__ uint32_t As[2][64 * TSTR];
    __shared__ uint32_t Bs[2][64 * TSTR];

    const int tid = threadIdx.x;
    const int lane = tid & 31;
    const int wid = tid >> 5;
    const int wr = wid >> 1;            // 0..1
    const int wc = wid & 1;             // 0..1
    const int row0 = blockIdx.y * 64;
    const int col0 = blockIdx.x * 64;

    float4 ra[2], rb[2];

    auto loadAB = [&](int kc) {
        const int k0 = kc * 16;
        #pragma unroll
        for (int l = 0; l < 2; l++) {
            int e = tid + (l << 7);
            int r = e >> 2, c = e & 3;
            ra[l] = *(const float4*)&A[(long)(row0 + r) * lda + k0 + (c << 2)];
            int br = col0 + r;
            if (br < Nn)
                rb[l] = *(const float4*)&Bt[(long)br * K + k0 + (c << 2)];
            else
                rb[l] = make_float4(0.f, 0.f, 0.f, 0.f);
        }
    };
    auto storeAB = [&](int buf) {
        #pragma unroll
        for (int l = 0; l < 2; l++) {
            int e = tid + (l << 7);
            int r = e >> 2, c = e & 3;
            uint32_t* ap = &As[buf][r * TSTR + (c << 2)];
            ap[0] = f2tf32(ra[l].x); ap[1] = f2tf32(ra[l].y);
            ap[2] = f2tf32(ra[l].z); ap[3] = f2tf32(ra[l].w);
            uint32_t* bp = &Bs[buf][r * TSTR + (c << 2)];
            bp[0] = f2tf32(rb[l].x); bp[1] = f2tf32(rb[l].y);
            bp[2] = f2tf32(rb[l].z); bp[3] = f2tf32(rb[l].w);
        }
    };

    float acc[2][4][4];
    #pragma unroll
    for (int mi = 0; mi < 2; mi++)
        #pragma unroll
        for (int ni = 0; ni < 4; ni++)
            #pragma unroll
            for (int e = 0; e < 4; e++) acc[mi][ni][e] = 0.f;

    const int NKT = K >> 4;
    loadAB(0);
    storeAB(0);
    __syncthreads();

    const int lg = lane >> 2;
    const int lt = lane & 3;

    for (int kc = 0; kc < NKT; kc++) {
        const int cur = kc & 1;
        if (kc + 1 < NKT) loadAB(kc + 1);

        #pragma unroll
        for (int ks = 0; ks < 2; ks++) {
            const int k0 = (ks << 3) + lt;
            uint32_t af[2][4], bf[4][2];
            #pragma unroll
            for (int mi = 0; mi < 2; mi++) {
                int rm = wr * 32 + mi * 16 + lg;
                af[mi][0] = As[cur][rm * TSTR + k0];
                af[mi][1] = As[cur][(rm + 8) * TSTR + k0];
                af[mi][2] = As[cur][rm * TSTR + k0 + 4];
                af[mi][3] = As[cur][(rm + 8) * TSTR + k0 + 4];
            }
            #pragma unroll
            for (int ni = 0; ni < 4; ni++) {
                int cn = wc * 32 + ni * 8 + lg;
                bf[ni][0] = Bs[cur][cn * TSTR + k0];
                bf[ni][1] = Bs[cur][cn * TSTR + k0 + 4];
            }
            #pragma unroll
            for (int mi = 0; mi < 2; mi++)
                #pragma unroll
                for (int ni = 0; ni < 4; ni++)
                    mma1688(acc[mi][ni], af[mi], bf[ni]);
        }

        if (kc + 1 < NKT) storeAB(cur ^ 1);
        __syncthreads();
    }

    #pragma unroll
    for (int mi = 0; mi < 2; mi++) {
        int gr0 = row0 + wr * 32 + mi * 16 + lg;
        #pragma unroll
        for (int ni = 0; ni < 4; ni++) {
            int gc = col0 + wc * 32 + ni * 8 + 2 * lt;
            if (gc < Nn) {
                float v0 = acc[mi][ni][0], v1 = acc[mi][ni][1];
                float v2 = acc[mi][ni][2], v3 = acc[mi][ni][3];
                if (EPI == 1) {
                    v0 = tanhf(v0); v1 = tanhf(v1); v2 = tanhf(v2); v3 = tanhf(v3);
                } else if (EPI == 2) {
                    float b0 = bias[gc], b1 = bias[gc + 1];
                    v0 = -expf(v0 + b0); v1 = -expf(v1 + b1);
                    v2 = -expf(v2 + b0); v3 = -expf(v3 + b1);
                }
                *(float2*)&Cm[(long)gr0 * ldc + gc] = make_float2(v0, v1);
                *(float2*)&Cm[(long)(gr0 + 8) * ldc + gc] = make_float2(v2, v3);
            }
        }
    }
}

// ---------------- weight transpose: dst[n*R + r] = src[r*Ncol + n] -----------
__global__ __launch_bounds__(256) void transpose_k(
    const float* __restrict__ src, float* __restrict__ dst, int R, int Ncol)
{
    __shared__ float t[32][33];
    const int bx = blockIdx.x * 32, by = blockIdx.y * 32;
    const int x = threadIdx.x, y = threadIdx.y;
    #pragma unroll
    for (int i = 0; i < 32; i += 8) {
        int r = by + y + i, n = bx + x;
        if (r < R && n < Ncol) t[y + i][x] = src[(long)r * Ncol + n];
    }
    __syncthreads();
    #pragma unroll
    for (int i = 0; i < 32; i += 8) {
        int n = bx + y + i, r = by + x;
        if (n < Ncol && r < R) dst[(long)n * R + r] = t[x][y + i];
    }
}

// ---------------- elementwise: time shift + maa_x mix ------------------------
__global__ void shift_kernel(const float* __restrict__ x,
                             const float* __restrict__ maa_x,
                             float* __restrict__ xx, float* __restrict__ xxx,
                             long total)
{
    long idx = (long)blockIdx.x * blockDim.x + threadIdx.x;
    if (idx >= total) return;
    int c = (int)(idx % C_);
    long rt = idx / C_;
    int t = (int)(rt % T_);
    float xv = x[idx];
    float xp = (t > 0) ? x[idx - C_] : 0.f;
    float d = xp - xv;
    xx[idx] = d;
    xxx[idx] = xv + d * maa_x[c];
}

// ---------------- fused: m_f = lora_f @ w2_f; x_f = x + xx*(maa_f + m_f) -----
__global__ __launch_bounds__(256) void mix5_fuse(
    const float* __restrict__ lora,
    const float* __restrict__ w2,
    const float* __restrict__ x, const float* __restrict__ xx,
    const float* __restrict__ maa_w, const float* __restrict__ maa_k,
    const float* __restrict__ maa_v, const float* __restrict__ maa_r,
    const float* __restrict__ maa_g,
    float* __restrict__ xw, float* __restrict__ xk, float* __restrict__ xv_,
    float* __restrict__ xr, float* __restrict__ xg)
{
    __shared__ float ls[32 * 160];
    __shared__ float ws[32 * 128];
    const int tid = threadIdx.x;
    const int rb = blockIdx.x * 32;
    const int cb = blockIdx.y * 128;

    for (int e = tid; e < 32 * 160; e += 256)
        ls[e] = lora[(long)(rb + e / 160) * 160 + (e % 160)];

    const int r = tid >> 3;
    const int j0 = (tid & 7) * 16;
    const long gbase = (long)(rb + r) * C_ + cb + j0;
    float xvv[16], xxv[16];
    #pragma unroll
    for (int jj = 0; jj < 16; jj += 4) {
        *(float4*)&xvv[jj] = *(const float4*)&x[gbase + jj];
        *(float4*)&xxv[jj] = *(const float4*)&xx[gbase + jj];
    }
    const float* maas[5] = { maa_w, maa_k, maa_v, maa_r, maa_g };
    float* outs[5] = { xw, xk, xv_, xr, xg };
    #pragma unroll
    for (int f = 0; f < 5; f++) {
        __syncthreads();
        for (int e = tid; e < 32 * 128; e += 256)
            ws[e] = w2[((long)f * 32 + e / 128) * 1024 + cb + (e & 127)];
        __syncthreads();
        float acc[16];
        #pragma unroll
        for (int jj = 0; jj < 16; jj++) acc[jj] = 0.f;
        #pragma unroll 8
        for (int d = 0; d < 32; d++) {
            float lv = ls[r * 160 + f * 32 + d];
            #pragma unroll
            for (int jj = 0; jj < 16; jj++)
                acc[jj] = fmaf(lv, ws[d * 128 + j0 + jj], acc[jj]);
        }
        const float* ma = maas[f];
        float* outp = outs[f];
        #pragma unroll
        for (int jj = 0; jj < 16; jj++) {
            float mm = ma[cb + j0 + jj] + acc[jj];
            acc[jj] = fmaf(xxv[jj], mm, xvv[jj]);
        }
        #pragma unroll
        for (int jj = 0; jj < 16; jj += 4)
            *(float4*)&outp[gbase + jj] = *(float4*)&acc[jj];
    }
}

// ---------------- chunked WKV6 -----------------------------------------------
__global__ __launch_bounds__(256) void wkv_chunkA(
    const float* __restrict__ r, const float* __restrict__ k,
    const float* __restrict__ v, const float* __restrict__ lw,
    const float* __restrict__ u,
    float* __restrict__ y, float* __restrict__ Dout,
    float* __restrict__ rpout, float* __restrict__ pLout)
{
    extern __shared__ float sm[];
    float* lp   = sm;
    float* bufA = lp + 65 * 64;
    float* rpT  = bufA + 64 * STRD;
    float* kpT  = rpT + 64 * STRD;
    float* kpp  = kpT + 64 * STRD;
    float* vsm  = kpp + 64 * STRD;
    float* dsm  = vsm + 64 * STRD;
    float* usm  = dsm + 64;

    const int tid = threadIdx.x;
    const int chunk = blockIdx.x;
    const int bh = chunk >> 5;
    const int c  = chunk & 31;
    const int b = bh >> 4, h = bh & 15;
    const long base = ((long)b * T_ + c * CHUNK) * C_ + h * 64;

    if (tid < 64) usm[tid] = u[h * 64 + tid];
    const int i  = tid & 63;
    const int tq = tid >> 6;

    #pragma unroll
    for (int e = 0; e < 16; e++) {
        int t = tq + 4 * e;
        bufA[t * STRD + i] = lw[base + (long)t * C_ + i];
    }
    __syncthreads();

    if (tid < 64) {
        float run = 0.f;
        for (int t = 0; t < 64; t++) {
            lp[t * 64 + tid] = run;
            run += bufA[t * STRD + tid];
        }
        lp[64 * 64 + tid] = run;
        pLout[(long)chunk * 64 + tid] = run;
    }
    __syncthreads();

    #pragma unroll
    for (int e = 0; e < 16; e++) {
        int t = tq + 4 * e;
        long gi = base + (long)t * C_ + i;
        float rr = r[gi], kk = k[gi];
        float lpti = lp[t * 64 + i];
        float lpn  = lpti + bufA[t * STRD + i];
        float lpL  = lp[64 * 64 + i];
        rpT[i * STRD + t] = rr * __expf(lpti);
        kpT[i * STRD + t] = kk * __expf(-lpn);
        kpp[t * STRD + i] = kk * __expf(lpL - lpn);
        vsm[t * STRD + i] = v[gi];
    }
    {
        int t = tid >> 2, q = tid & 3;
        long gb = base + (long)t * C_;
        float p = 0.f;
        #pragma unroll
        for (int ii = 0; ii < 16; ii++) {
            int ci = q * 16 + ii;
            p += r[gb + ci] * usm[ci] * k[gb + ci];
        }
        p += __shfl_xor_sync(0xffffffffu, p, 1);
        p += __shfl_xor_sync(0xffffffffu, p, 2);
        if (q == 0) dsm[t] = p;
    }
    __syncthreads();

    {
        float* rpg = rpout + (long)chunk * 64 * 64;
        #pragma unroll
        for (int e = 0; e < 16; e++) {
            int flat = tid + 256 * e;
            rpg[flat] = rpT[(flat >> 6) * STRD + (flat & 63)];
        }
    }

    {
        int t0 = (tid >> 4) * 4, s0 = (tid & 15) * 4;
        float acc[4][4];
        #pragma unroll
        for (int a = 0; a < 4; a++)
            #pragma unroll
            for (int bq = 0; bq < 4; bq++) acc[a][bq] = 0.f;
        for (int ii = 0; ii < 64; ii++) {
            float4 a4 = *(const float4*)&rpT[ii * STRD + t0];
            float4 b4 = *(const float4*)&kpT[ii * STRD + s0];
            float av[4] = { a4.x, a4.y, a4.z, a4.w };
            float bv[4] = { b4.x, b4.y, b4.z, b4.w };
            #pragma unroll
            for (int a = 0; a < 4; a++)
                #pragma unroll
                for (int bq = 0; bq < 4; bq++)
                    acc[a][bq] = fmaf(av[a], bv[bq], acc[a][bq]);
        }
        __syncthreads();
        #pragma unroll
        for (int a = 0; a < 4; a++)
            #pragma unroll
            for (int bq = 0; bq < 4; bq++) {
                int tt = t0 + a, ss = s0 + bq;
                float val = (tt > ss) ? acc[a][bq] : ((tt == ss) ? dsm[tt] : 0.f);
                bufA[ss * STRD + tt] = val;
            }
    }
    __syncthreads();

    {
        int t0 = (tid >> 4) * 4, j0 = (tid & 15) * 4;
        float acc[4][4];
        #pragma unroll
        for (int a = 0; a < 4; a++)
            #pragma unroll
            for (int bq = 0; bq < 4; bq++) acc[a][bq] = 0.f;
        for (int s = 0; s < 64; s++) {
            float4 a4 = *(const float4*)&bufA[s * STRD + t0];
            float4 b4 = *(const float4*)&vsm[s * STRD + j0];
            float av[4] = { a4.x, a4.y, a4.z, a4.w };
            float bv[4] = { b4.x, b4.y, b4.z, b4.w };
            #pragma unroll
            for (int a = 0; a < 4; a++)
                #pragma unroll
                for (int bq = 0; bq < 4; bq++)
                    acc[a][bq] = fmaf(av[a], bv[bq], acc[a][bq]);
        }
        #pragma unroll
        for (int a = 0; a < 4; a++) {
            float4 o = make_float4(acc[a][0], acc[a][1], acc[a][2], acc[a][3]);
            *(float4*)&y[base + (long)(t0 + a) * C_ + j0] = o;
        }
    }

    {
        int i0 = (tid >> 4) * 4, j0 = (tid & 15) * 4;
        float acc[4][4];
        #pragma unroll
        for (int a = 0; a < 4; a++)
            #pragma unroll
            for (int bq = 0; bq < 4; bq++) acc[a][bq] = 0.f;
        for (int s = 0; s < 64; s++) {
            float4 a4 = *(const float4*)&kpp[s * STRD + i0];
            float4 b4 = *(const float4*)&vsm[s * STRD + j0];
            float av[4] = { a4.x, a4.y, a4.z, a4.w };
            float bv[4] = { b4.x, b4.y, b4.z, b4.w };
            #pragma unroll
            for (int a = 0; a < 4; a++)
                #pragma unroll
                for (int bq = 0; bq < 4; bq++)
                    acc[a][bq] = fmaf(av[a], bv[bq], acc[a][bq]);
        }
        float* Dp = Dout + (long)chunk * 4096;
        #pragma unroll
        for (int a = 0; a < 4; a++) {
            float4 o = make_float4(acc[a][0], acc[a][1], acc[a][2], acc[a][3]);
            *(float4*)&Dp[(i0 + a) * 64 + j0] = o;
        }
    }
}

__global__ __launch_bounds__(256) void wkv_chunkB(
    const float* __restrict__ D, const float* __restrict__ pL,
    float* __restrict__ S)
{
    const int bh = blockIdx.x;
    const int tid = threadIdx.x;
    const int i = tid >> 2;
    const int jb = (tid & 3) * 16;
    float4 s0 = {0,0,0,0}, s1 = {0,0,0,0}, s2 = {0,0,0,0}, s3 = {0,0,0,0};
    for (int c = 0; c < G_; c++) {
        long chunk = (long)bh * G_ + c;
        long off = chunk * 4096 + i * 64 + jb;
        *(float4*)&S[off + 0]  = s0;
        *(float4*)&S[off + 4]  = s1;
        *(float4*)&S[off + 8]  = s2;
        *(float4*)&S[off + 12] = s3;
        float pl = __expf(pL[chunk * 64 + i]);
        float4 d0 = *(const float4*)&D[off + 0];
        float4 d1 = *(const float4*)&D[off + 4];
        float4 d2 = *(const float4*)&D[off + 8];
        float4 d3 = *(const float4*)&D[off + 12];
        s0 = make_float4(fmaf(pl, s0.x, d0.x), fmaf(pl, s0.y, d0.y), fmaf(pl, s0.z, d0.z), fmaf(pl, s0.w, d0.w));
        s1 = make_float4(fmaf(pl, s1.x, d1.x), fmaf(pl, s1.y, d1.y), fmaf(pl, s1.z, d1.z), fmaf(pl, s1.w, d1.w));
        s2 = make_float4(fmaf(pl, s2.x, d2.x), fmaf(pl, s2.y, d2.y), fmaf(pl, s2.z, d2.z), fmaf(pl, s2.w, d2.w));
        s3 = make_float4(fmaf(pl, s3.x, d3.x), fmaf(pl, s3.y, d3.y), fmaf(pl, s3.z, d3.z), fmaf(pl, s3.w, d3.w));
    }
}

__global__ __launch_bounds__(256) void wkv_chunkC(
    const float* __restrict__ rp, const float* __restrict__ S,
    float* __restrict__ y)
{
    __shared__ float rps[64 * 64];
    __shared__ float Ss[64 * 64];
    const int tid = threadIdx.x;
    const int chunk = blockIdx.x;
    const int bh = chunk >> 5;
    const int c  = chunk & 31;
    const int b = bh >> 4, h = bh & 15;
    const long base = ((long)b * T_ + c * CHUNK) * C_ + h * 64;

    const float* rpg = rp + (long)chunk * 4096;
    const float* Sg  = S  + (long)chunk * 4096;
    #pragma unroll
    for (int e = 0; e < 4; e++) {
        int f4 = tid + 256 * e;
        *(float4*)&rps[f4 * 4] = *(const float4*)&rpg[f4 * 4];
        *(float4*)&Ss[f4 * 4]  = *(const float4*)&Sg[f4 * 4];
    }
    __syncthreads();

    int t0 = (tid >> 4) * 4, j0 = (tid & 15) * 4;
    float acc[4][4];
    #pragma unroll
    for (int a = 0; a < 4; a++)
        #pragma unroll
        for (int bq = 0; bq < 4; bq++) acc[a][bq] = 0.f;
    for (int ii = 0; ii < 64; ii++) {
        float4 a4 = *(const float4*)&rps[ii * 64 + t0];
        float4 b4 = *(const float4*)&Ss[ii * 64 + j0];
        float av[4] = { a4.x, a4.y, a4.z, a4.w };
        float bv[4] = { b4.x, b4.y, b4.z, b4.w };
        #pragma unroll
        for (int a = 0; a < 4; a++)
            #pragma unroll
            for (int bq = 0; bq < 4; bq++)
                acc[a][bq] = fmaf(av[a], bv[bq], acc[a][bq]);
    }
    #pragma unroll
    for (int a = 0; a < 4; a++) {
        long yo = base + (long)(t0 + a) * C_ + j0;
        float4 cur = *(const float4*)&y[yo];
        cur.x += acc[a][0]; cur.y += acc[a][1];
        cur.z += acc[a][2]; cur.w += acc[a][3];
        *(float4*)&y[yo] = cur;
    }
}

// ---------------- GroupNorm over heads + gate multiply -----------------------
__global__ __launch_bounds__(512) void gn_kernel(
    const float* __restrict__ y, const float* __restrict__ ln_g,
    const float* __restrict__ ln_b, const float* __restrict__ g,
    float* __restrict__ z)
{
    const int bt = blockIdx.x;
    const int warp = threadIdx.x >> 5;
    const int lane = threadIdx.x & 31;
    const long base = (long)bt * C_ + warp * 64;

    float a0 = y[base + lane];
    float a1 = y[base + 32 + lane];
    float sum = a0 + a1;
    float sq = a0 * a0 + a1 * a1;
    #pragma unroll
    for (int off = 16; off > 0; off >>= 1) {
        sum += __shfl_xor_sync(0xffffffffu, sum, off);
        sq  += __shfl_xor_sync(0xffffffffu, sq,  off);
    }
    float mu = sum * (1.f / 64.f);
    float var = sq * (1.f / 64.f) - mu * mu;
    float inv = rsqrtf(var + 6.4e-4f);

    int c0 = warp * 64 + lane;
    float z0 = (a0 - mu) * inv * ln_g[c0] + ln_b[c0];
    float z1 = (a1 - mu) * inv * ln_g[c0 + 32] + ln_b[c0 + 32];
    z[base + lane]      = z0 * g[base + lane];
    z[base + 32 + lane] = z1 * g[base + 32 + lane];
}

// ---------------- launcher ----------------------------------------------------
extern "C" void kernel_launch(void* const* d_in, const int* in_sizes, int n_in,
                              void* d_out, int out_size)
{
    const float* x          = (const float*)d_in[0];
    const float* maa_x      = (const float*)d_in[1];
    const float* maa_w      = (const float*)d_in[2];
    const float* maa_k      = (const float*)d_in[3];
    const float* maa_v      = (const float*)d_in[4];
    const float* maa_r      = (const float*)d_in[5];
    const float* maa_g      = (const float*)d_in[6];
    const float* maa_w1     = (const float*)d_in[7];
    const float* maa_w2     = (const float*)d_in[8];
    const float* Wr         = (const float*)d_in[9];
    const float* Wk         = (const float*)d_in[10];
    const float* Wv         = (const float*)d_in[11];
    const float* Wo         = (const float*)d_in[12];
    const float* gate_w1    = (const float*)d_in[13];
    const float* gate_w2    = (const float*)d_in[14];
    const float* time_decay = (const float*)d_in[15];
    const float* decay_w1   = (const float*)d_in[16];
    const float* decay_w2   = (const float*)d_in[17];
    const float* u          = (const float*)d_in[18];
    const float* ln_g       = (const float*)d_in[19];
    const float* ln_b       = (const float*)d_in[20];
    (void)in_sizes; (void)n_in; (void)out_size;

    float *p_xx, *p_xxx, *p_xw, *p_xk, *p_xv, *p_xr, *p_xg;
    float *p_r, *p_k, *p_v, *p_w, *p_g, *p_y, *p_z, *p_lora, *p_small;
    float *p_D, *p_Sc, *p_rp, *p_pL;
    float *p_WrT, *p_WkT, *p_WvT, *p_WoT, *p_w1T, *p_dw1T, *p_gw1T, *p_dw2T, *p_gw2T;
    cudaGetSymbolAddress((void**)&p_xx, g_xx);
    cudaGetSymbolAddress((void**)&p_xxx, g_xxx);
    cudaGetSymbolAddress((void**)&p_xw, g_xw);
    cudaGetSymbolAddress((void**)&p_xk, g_xk);
    cudaGetSymbolAddress((void**)&p_xv, g_xv);
    cudaGetSymbolAddress((void**)&p_xr, g_xr);
    cudaGetSymbolAddress((void**)&p_xg, g_xg);
    cudaGetSymbolAddress((void**)&p_r, g_r);
    cudaGetSymbolAddress((void**)&p_k, g_k);
    cudaGetSymbolAddress((void**)&p_v, g_v);
    cudaGetSymbolAddress((void**)&p_w, g_w);
    cudaGetSymbolAddress((void**)&p_g, g_g);
    cudaGetSymbolAddress((void**)&p_y, g_y);
    cudaGetSymbolAddress((void**)&p_z, g_z);
    cudaGetSymbolAddress((void**)&p_lora, g_lora);
    cudaGetSymbolAddress((void**)&p_small, g_small);
    cudaGetSymbolAddress((void**)&p_D, g_D);
    cudaGetSymbolAddress((void**)&p_Sc, g_Sc);
    cudaGetSymbolAddress((void**)&p_rp, g_rp);
    cudaGetSymbolAddress((void**)&p_pL, g_pL);
    cudaGetSymbolAddress((void**)&p_WrT, g_WrT);
    cudaGetSymbolAddress((void**)&p_WkT, g_WkT);
    cudaGetSymbolAddress((void**)&p_WvT, g_WvT);
    cudaGetSymbolAddress((void**)&p_WoT, g_WoT);
    cudaGetSymbolAddress((void**)&p_w1T, g_w1T);
    cudaGetSymbolAddress((void**)&p_dw1T, g_dw1T);
    cudaGetSymbolAddress((void**)&p_gw1T, g_gw1T);
    cudaGetSymbolAddress((void**)&p_dw2T, g_dw2T);
    cudaGetSymbolAddress((void**)&p_gw2T, g_gw2T);

    const long total = BTC;
    const int M = B_ * T_;          // 8192
    const int gy = M / 128;         // 64
    const int gy64 = M / 64;        // 128

    const int SMEM_A = (65 * 64 + 5 * 64 * STRD + 128) * 4;
    cudaFuncSetAttribute(wkv_chunkA, cudaFuncAttributeMaxDynamicSharedMemorySize, SMEM_A);

    // ---- ordered so launch index 5 (-s 5 -c 1) is the big r-projection GEMM --
    // 0. time shift + maa_x mix
    shift_kernel<<<(int)((total + 255) / 256), 256>>>(x, maa_x, p_xx, p_xxx, total);
    // 1. transpose maa_w1
    transpose_k<<<dim3(5, 32), dim3(32, 8)>>>(maa_w1, p_w1T, C_, 160);
    // 2. lora = tanh(xxx @ maa_w1)   N=160 (small-tile kernel)
    gemm_tc64<1><<<dim3(3, gy64), 128>>>(p_xxx, C_, p_w1T, p_lora, 160, C_, 160, nullptr);
    // 3. fused mix GEMMs + token-shift blend
    mix5_fuse<<<dim3(M / 32, C_ / 128), 256>>>(p_lora, maa_w2, x, p_xx,
        maa_w, maa_k, maa_v, maa_r, maa_g,
        p_xw, p_xk, p_xv, p_xr, p_xg);
    // 4. transpose Wr
    transpose_k<<<dim3(32, 32), dim3(32, 8)>>>(Wr, p_WrT, C_, C_);
    // 5. r projection  <-- ncu captures this one
    gemm_tc<0><<<dim3(8, gy), 256>>>(p_xr, C_, p_WrT, p_r, C_, C_, C_, nullptr);
    // 6-9. k, v projections
    transpose_k<<<dim3(32, 32), dim3(32, 8)>>>(Wk, p_WkT, C_, C_);
    gemm_tc<0><<<dim3(8, gy), 256>>>(p_xk, C_, p_WkT, p_k, C_, C_, C_, nullptr);
    transpose_k<<<dim3(32, 32), dim3(32, 8)>>>(Wv, p_WvT, C_, C_);
    gemm_tc<0><<<dim3(8, gy), 256>>>(p_xv, C_, p_WvT, p_v, C_, C_, C_, nullptr);
    // 10-13. decay: lw = -exp(time_decay + tanh(xw@decay_w1)@decay_w2)
    transpose_k<<<dim3(2, 32), dim3(32, 8)>>>(decay_w1, p_dw1T, C_, 64);
    gemm_tc64<1><<<dim3(1, gy64), 128>>>(p_xw, C_, p_dw1T, p_small, 64, C_, 64, nullptr);
    transpose_k<<<dim3(32, 2), dim3(32, 8)>>>(decay_w2, p_dw2T, 64, C_);
    gemm_tc<2><<<dim3(8, gy), 256>>>(p_small, 64, p_dw2T, p_w, C_, 64, C_, time_decay);
    // 14-16. chunked WKV6
    wkv_chunkA<<<NCHUNK, 256, SMEM_A>>>(p_r, p_k, p_v, p_w, u,
                                        p_y, p_D, p_rp, p_pL);
    wkv_chunkB<<<B_ * H_, 256>>>(p_D, p_pL, p_Sc);
    wkv_chunkC<<<NCHUNK, 256>>>(p_rp, p_Sc, p_y);
    // 17-20. gate
    transpose_k<<<dim3(2, 32), dim3(32, 8)>>>(gate_w1,  p_gw1T, C_, 64);
    gemm_tc64<1><<<dim3(1, gy64), 128>>>(p_xg, C_, p_gw1T, p_small, 64, C_, 64, nullptr);
    transpose_k<<<dim3(32, 2), dim3(32, 8)>>>(gate_w2,  p_gw2T, 64, C_);
    gemm_tc<0><<<dim3(8, gy), 256>>>(p_small, 64, p_gw2T, p_g, C_, 64, C_, nullptr);
    // 21. GroupNorm + gate multiply
    gn_kernel<<<M, 512>>>(p_y, ln_g, ln_b, p_g, p_z);
    // 22-23. out = z @ Wo
    transpose_k<<<dim3(32, 32), dim3(32, 8)>>>(Wo, p_WoT, C_, C_);
    gemm_tc<0><<<dim3(8, gy), 256>>>(p_z, C_, p_WoT, (float*)d_out, C_, C_, C_, nullptr);
}

// round 6
// speedup vs baseline: 3.4473x; 1.4232x over previous
#include <cuda_runtime.h>
#include <cuda_bf16.h>
#include <cstdint>
#include <math.h>

// Problem constants
#define B_  4
#define T_  2048
#define C_  1024
#define H_  16
#define N_  64
#define DMIX 32
#define DGATE 64
#define DDECAY 64

#define CHUNK 64
#define G_ 32                     // chunks per (b,h)
#define NCHUNK (B_*H_*G_)         // 2048
#define STRD 68                   // padded row stride for chunk smem tiles

static const long BTC = (long)B_ * T_ * C_;   // 8388608

// ---------------- scratch (device globals; no runtime allocation) -------------
__device__ float g_xx [ (long)B_*T_*C_ ];
__device__ float g_xxx[ (long)B_*T_*C_ ];
__device__ float g_xw [ (long)B_*T_*C_ ];
__device__ float g_xk [ (long)B_*T_*C_ ];
__device__ float g_xv [ (long)B_*T_*C_ ];
__device__ float g_xr [ (long)B_*T_*C_ ];
__device__ float g_xg [ (long)B_*T_*C_ ];
__device__ float g_r  [ (long)B_*T_*C_ ];
__device__ float g_k  [ (long)B_*T_*C_ ];
__device__ float g_v  [ (long)B_*T_*C_ ];
__device__ float g_w  [ (long)B_*T_*C_ ];   // stores lw = log(decay)
__device__ float g_g  [ (long)B_*T_*C_ ];
__device__ float g_y  [ (long)B_*T_*C_ ];
__device__ float g_z  [ (long)B_*T_*C_ ];
__device__ float g_lora [ (long)B_*T_*5*DMIX ];
__device__ float g_small[ (long)B_*T_*64 ];
__device__ float g_D  [ (long)NCHUNK*64*64 ];
__device__ float g_Sc [ (long)NCHUNK*64*64 ];
__device__ float g_rp [ (long)NCHUNK*64*64 ];
__device__ float g_pL [ (long)NCHUNK*64 ];
// transposed weights [N, K] K-major
__device__ float g_WrT[ (long)C_*C_ ];
__device__ float g_WkT[ (long)C_*C_ ];
__device__ float g_WvT[ (long)C_*C_ ];
__device__ float g_WoT[ (long)C_*C_ ];
__device__ float g_w1T[ (long)160*C_ ];
__device__ float g_w2T[ (long)C_*160 ];
__device__ float g_dw1T[ (long)64*C_ ];
__device__ float g_gw1T[ (long)64*C_ ];
__device__ float g_dw2T[ (long)C_*64 ];
__device__ float g_gw2T[ (long)C_*64 ];

// ================= tf32 mma.sync GEMM ========================================
#define TSTR 20   // smem row stride (16 + 4 pad) -> conflict-free fragments

__device__ __forceinline__ uint32_t f2tf32(float f) {
    uint32_t o;
    asm("cvt.rna.tf32.f32 %0, %1;" : "=r"(o) : "f"(f));
    return o;
}
__device__ __forceinline__ void mma1688(float* d, const uint32_t* a, const uint32_t* b) {
    asm volatile(
        "mma.sync.aligned.m16n8k8.row.col.f32.tf32.tf32.f32 "
        "{%0,%1,%2,%3}, {%4,%5,%6,%7}, {%8,%9}, {%0,%1,%2,%3};"
        : "+f"(d[0]), "+f"(d[1]), "+f"(d[2]), "+f"(d[3])
        : "r"(a[0]), "r"(a[1]), "r"(a[2]), "r"(a[3]), "r"(b[0]), "r"(b[1]));
}

// ---- big tile: BM=128, BN=128, BK=16, 256 threads (8 warps 2x4, warp 64x32) --
// EPI: 0 none, 1 tanh, 2 -exp(acc + bias[col]), 3 xin + xxin*(bias[col] + acc)
template<int EPI>
__global__ __launch_bounds__(256) void gemm_tc(
    const float* __restrict__ A, int lda,
    const float* __restrict__ Bt, int ldb,   // [Nn rows, >=K cols] K-major
    float* __restrict__ Cm, int ldc,
    int K, int Nn, const float* __restrict__ bias,
    const float* __restrict__ xin, const float* __restrict__ xxin)
{
    __shared__ uint32_t As[2][128 * TSTR];
    __shared__ uint32_t Bs[2][128 * TSTR];

    const int tid = threadIdx.x;
    const int lane = tid & 31;
    const int wid = tid >> 5;
    const int wr = wid >> 2;
    const int wc = wid & 3;
    const int row0 = blockIdx.y * 128;
    const int col0 = blockIdx.x * 128;

    float4 ra[2], rb[2];

    auto loadAB = [&](int kc) {
        const int k0 = kc * 16;
        #pragma unroll
        for (int l = 0; l < 2; l++) {
            int e = tid + (l << 8);
            int r = e >> 2, c = e & 3;
            ra[l] = *(const float4*)&A[(long)(row0 + r) * lda + k0 + (c << 2)];
            int br = col0 + r;
            if (br < Nn)
                rb[l] = *(const float4*)&Bt[(long)br * ldb + k0 + (c << 2)];
            else
                rb[l] = make_float4(0.f, 0.f, 0.f, 0.f);
        }
    };
    auto storeAB = [&](int buf) {
        #pragma unroll
        for (int l = 0; l < 2; l++) {
            int e = tid + (l << 8);
            int r = e >> 2, c = e & 3;
            uint32_t* ap = &As[buf][r * TSTR + (c << 2)];
            ap[0] = f2tf32(ra[l].x); ap[1] = f2tf32(ra[l].y);
            ap[2] = f2tf32(ra[l].z); ap[3] = f2tf32(ra[l].w);
            uint32_t* bp = &Bs[buf][r * TSTR + (c << 2)];
            bp[0] = f2tf32(rb[l].x); bp[1] = f2tf32(rb[l].y);
            bp[2] = f2tf32(rb[l].z); bp[3] = f2tf32(rb[l].w);
        }
    };

    float acc[4][4][4];
    #pragma unroll
    for (int mi = 0; mi < 4; mi++)
        #pragma unroll
        for (int ni = 0; ni < 4; ni++)
            #pragma unroll
            for (int e = 0; e < 4; e++) acc[mi][ni][e] = 0.f;

    const int NKT = K >> 4;
    loadAB(0);
    storeAB(0);
    __syncthreads();

    const int lg = lane >> 2;
    const int lt = lane & 3;

    for (int kc = 0; kc < NKT; kc++) {
        const int cur = kc & 1;
        if (kc + 1 < NKT) loadAB(kc + 1);

        #pragma unroll
        for (int ks = 0; ks < 2; ks++) {
            const int k0 = (ks << 3) + lt;
            uint32_t af[4][4], bf[4][2];
            #pragma unroll
            for (int mi = 0; mi < 4; mi++) {
                int rm = wr * 64 + mi * 16 + lg;
                af[mi][0] = As[cur][rm * TSTR + k0];
                af[mi][1] = As[cur][(rm + 8) * TSTR + k0];
                af[mi][2] = As[cur][rm * TSTR + k0 + 4];
                af[mi][3] = As[cur][(rm + 8) * TSTR + k0 + 4];
            }
            #pragma unroll
            for (int ni = 0; ni < 4; ni++) {
                int cn = wc * 32 + ni * 8 + lg;
                bf[ni][0] = Bs[cur][cn * TSTR + k0];
                bf[ni][1] = Bs[cur][cn * TSTR + k0 + 4];
            }
            #pragma unroll
            for (int mi = 0; mi < 4; mi++)
                #pragma unroll
                for (int ni = 0; ni < 4; ni++)
                    mma1688(acc[mi][ni], af[mi], bf[ni]);
        }

        if (kc + 1 < NKT) storeAB(cur ^ 1);
        __syncthreads();
    }

    #pragma unroll
    for (int mi = 0; mi < 4; mi++) {
        int gr0 = row0 + wr * 64 + mi * 16 + lg;
        #pragma unroll
        for (int ni = 0; ni < 4; ni++) {
            int gc = col0 + wc * 32 + ni * 8 + 2 * lt;
            if (gc < Nn) {
                float v0 = acc[mi][ni][0], v1 = acc[mi][ni][1];
                float v2 = acc[mi][ni][2], v3 = acc[mi][ni][3];
                long o0 = (long)gr0 * ldc + gc;
                long o1 = (long)(gr0 + 8) * ldc + gc;
                if (EPI == 1) {
                    v0 = tanhf(v0); v1 = tanhf(v1); v2 = tanhf(v2); v3 = tanhf(v3);
                } else if (EPI == 2) {
                    float b0 = bias[gc], b1 = bias[gc + 1];
                    v0 = -expf(v0 + b0); v1 = -expf(v1 + b1);
                    v2 = -expf(v2 + b0); v3 = -expf(v3 + b1);
                } else if (EPI == 3) {
                    float b0 = bias[gc], b1 = bias[gc + 1];
                    float2 x0 = *(const float2*)&xin[o0];
                    float2 x1 = *(const float2*)&xin[o1];
                    float2 d0 = *(const float2*)&xxin[o0];
                    float2 d1 = *(const float2*)&xxin[o1];
                    v0 = fmaf(d0.x, b0 + v0, x0.x);
                    v1 = fmaf(d0.y, b1 + v1, x0.y);
                    v2 = fmaf(d1.x, b0 + v2, x1.x);
                    v3 = fmaf(d1.y, b1 + v3, x1.y);
                }
                *(float2*)&Cm[o0] = make_float2(v0, v1);
                *(float2*)&Cm[o1] = make_float2(v2, v3);
            }
        }
    }
}

// ---- small tile: BM=64, BN=64, BK=16, 128 threads (4 warps 2x2, warp 32x32) --
template<int EPI>
__global__ __launch_bounds__(128) void gemm_tc64(
    const float* __restrict__ A, int lda,
    const float* __restrict__ Bt, int ldb,
    float* __restrict__ Cm, int ldc,
    int K, int Nn, const float* __restrict__ bias)
{
    __shared__ uint32_t As[2][64 * TSTR];
    __shared__ uint32_t Bs[2][64 * TSTR];

    const int tid = threadIdx.x;
    const int lane = tid & 31;
    const int wid = tid >> 5;
    const int wr = wid >> 1;
    const int wc = wid & 1;
    const int row0 = blockIdx.y * 64;
    const int col0 = blockIdx.x * 64;

    float4 ra[2], rb[2];

    auto loadAB = [&](int kc) {
        const int k0 = kc * 16;
        #pragma unroll
        for (int l = 0; l < 2; l++) {
            int e = tid + (l << 7);
            int r = e >> 2, c = e & 3;
            ra[l] = *(const float4*)&A[(long)(row0 + r) * lda + k0 + (c << 2)];
            int br = col0 + r;
            if (br < Nn)
                rb[l] = *(const float4*)&Bt[(long)br * ldb + k0 + (c << 2)];
            else
                rb[l] = make_float4(0.f, 0.f, 0.f, 0.f);
        }
    };
    auto storeAB = [&](int buf) {
        #pragma unroll
        for (int l = 0; l < 2; l++) {
            int e = tid + (l << 7);
            int r = e >> 2, c = e & 3;
            uint32_t* ap = &As[buf][r * TSTR + (c << 2)];
            ap[0] = f2tf32(ra[l].x); ap[1] = f2tf32(ra[l].y);
            ap[2] = f2tf32(ra[l].z); ap[3] = f2tf32(ra[l].w);
            uint32_t* bp = &Bs[buf][r * TSTR + (c << 2)];
            bp[0] = f2tf32(rb[l].x); bp[1] = f2tf32(rb[l].y);
            bp[2] = f2tf32(rb[l].z); bp[3] = f2tf32(rb[l].w);
        }
    };

    float acc[2][4][4];
    #pragma unroll
    for (int mi = 0; mi < 2; mi++)
        #pragma unroll
        for (int ni = 0; ni < 4; ni++)
            #pragma unroll
            for (int e = 0; e < 4; e++) acc[mi][ni][e] = 0.f;

    const int NKT = K >> 4;
    loadAB(0);
    storeAB(0);
    __syncthreads();

    const int lg = lane >> 2;
    const int lt = lane & 3;

    for (int kc = 0; kc < NKT; kc++) {
        const int cur = kc & 1;
        if (kc + 1 < NKT) loadAB(kc + 1);

        #pragma unroll
        for (int ks = 0; ks < 2; ks++) {
            const int k0 = (ks << 3) + lt;
            uint32_t af[2][4], bf[4][2];
            #pragma unroll
            for (int mi = 0; mi < 2; mi++) {
                int rm = wr * 32 + mi * 16 + lg;
                af[mi][0] = As[cur][rm * TSTR + k0];
                af[mi][1] = As[cur][(rm + 8) * TSTR + k0];
                af[mi][2] = As[cur][rm * TSTR + k0 + 4];
                af[mi][3] = As[cur][(rm + 8) * TSTR + k0 + 4];
            }
            #pragma unroll
            for (int ni = 0; ni < 4; ni++) {
                int cn = wc * 32 + ni * 8 + lg;
                bf[ni][0] = Bs[cur][cn * TSTR + k0];
                bf[ni][1] = Bs[cur][cn * TSTR + k0 + 4];
            }
            #pragma unroll
            for (int mi = 0; mi < 2; mi++)
                #pragma unroll
                for (int ni = 0; ni < 4; ni++)
                    mma1688(acc[mi][ni], af[mi], bf[ni]);
        }

        if (kc + 1 < NKT) storeAB(cur ^ 1);
        __syncthreads();
    }

    #pragma unroll
    for (int mi = 0; mi < 2; mi++) {
        int gr0 = row0 + wr * 32 + mi * 16 + lg;
        #pragma unroll
        for (int ni = 0; ni < 4; ni++) {
            int gc = col0 + wc * 32 + ni * 8 + 2 * lt;
            if (gc < Nn) {
                float v0 = acc[mi][ni][0], v1 = acc[mi][ni][1];
                float v2 = acc[mi][ni][2], v3 = acc[mi][ni][3];
                if (EPI == 1) {
                    v0 = tanhf(v0); v1 = tanhf(v1); v2 = tanhf(v2); v3 = tanhf(v3);
                } else if (EPI == 2) {
                    float b0 = bias[gc], b1 = bias[gc + 1];
                    v0 = -expf(v0 + b0); v1 = -expf(v1 + b1);
                    v2 = -expf(v2 + b0); v3 = -expf(v3 + b1);
                }
                *(float2*)&Cm[(long)gr0 * ldc + gc] = make_float2(v0, v1);
                *(float2*)&Cm[(long)(gr0 + 8) * ldc + gc] = make_float2(v2, v3);
            }
        }
    }
}

// ---------------- weight transpose: dst[n*R + r] = src[r*Ncol + n] -----------
__global__ __launch_bounds__(256) void transpose_k(
    const float* __restrict__ src, float* __restrict__ dst, int R, int Ncol)
{
    __shared__ float t[32][33];
    const int bx = blockIdx.x * 32, by = blockIdx.y * 32;
    const int x = threadIdx.x, y = threadIdx.y;
    #pragma unroll
    for (int i = 0; i < 32; i += 8) {
        int r = by + y + i, n = bx + x;
        if (r < R && n < Ncol) t[y + i][x] = src[(long)r * Ncol + n];
    }
    __syncthreads();
    #pragma unroll
    for (int i = 0; i < 32; i += 8) {
        int n = bx + y + i, r = by + x;
        if (n < Ncol && r < R) dst[(long)n * R + r] = t[x][y + i];
    }
}

// ---------------- elementwise: time shift + maa_x mix ------------------------
__global__ void shift_kernel(const float* __restrict__ x,
                             const float* __restrict__ maa_x,
                             float* __restrict__ xx, float* __restrict__ xxx,
                             long total)
{
    long idx = (long)blockIdx.x * blockDim.x + threadIdx.x;
    if (idx >= total) return;
    int c = (int)(idx % C_);
    long rt = idx / C_;
    int t = (int)(rt % T_);
    float xv = x[idx];
    float xp = (t > 0) ? x[idx - C_] : 0.f;
    float d = xp - xv;
    xx[idx] = d;
    xxx[idx] = xv + d * maa_x[c];
}

// ---------------- chunked WKV6 -----------------------------------------------
__global__ __launch_bounds__(256) void wkv_chunkA(
    const float* __restrict__ r, const float* __restrict__ k,
    const float* __restrict__ v, const float* __restrict__ lw,
    const float* __restrict__ u,
    float* __restrict__ y, float* __restrict__ Dout,
    float* __restrict__ rpout, float* __restrict__ pLout)
{
    extern __shared__ float sm[];
    float* lp   = sm;
    float* bufA = lp + 65 * 64;
    float* rpT  = bufA + 64 * STRD;
    float* kpT  = rpT + 64 * STRD;
    float* kpp  = kpT + 64 * STRD;
    float* vsm  = kpp + 64 * STRD;
    float* dsm  = vsm + 64 * STRD;
    float* usm  = dsm + 64;

    const int tid = threadIdx.x;
    const int chunk = blockIdx.x;
    const int bh = chunk >> 5;
    const int c  = chunk & 31;
    const int b = bh >> 4, h = bh & 15;
    const long base = ((long)b * T_ + c * CHUNK) * C_ + h * 64;

    if (tid < 64) usm[tid] = u[h * 64 + tid];
    const int i  = tid & 63;
    const int tq = tid >> 6;

    #pragma unroll
    for (int e = 0; e < 16; e++) {
        int t = tq + 4 * e;
        bufA[t * STRD + i] = lw[base + (long)t * C_ + i];
    }
    __syncthreads();

    if (tid < 64) {
        float run = 0.f;
        for (int t = 0; t < 64; t++) {
            lp[t * 64 + tid] = run;
            run += bufA[t * STRD + tid];
        }
        lp[64 * 64 + tid] = run;
        pLout[(long)chunk * 64 + tid] = run;
    }
    __syncthreads();

    #pragma unroll
    for (int e = 0; e < 16; e++) {
        int t = tq + 4 * e;
        long gi = base + (long)t * C_ + i;
        float rr = r[gi], kk = k[gi];
        float lpti = lp[t * 64 + i];
        float lpn  = lpti + bufA[t * STRD + i];
        float lpL  = lp[64 * 64 + i];
        rpT[i * STRD + t] = rr * __expf(lpti);
        kpT[i * STRD + t] = kk * __expf(-lpn);
        kpp[t * STRD + i] = kk * __expf(lpL - lpn);
        vsm[t * STRD + i] = v[gi];
    }
    {
        int t = tid >> 2, q = tid & 3;
        long gb = base + (long)t * C_;
        float p = 0.f;
        #pragma unroll
        for (int ii = 0; ii < 16; ii++) {
            int ci = q * 16 + ii;
            p += r[gb + ci] * usm[ci] * k[gb + ci];
        }
        p += __shfl_xor_sync(0xffffffffu, p, 1);
        p += __shfl_xor_sync(0xffffffffu, p, 2);
        if (q == 0) dsm[t] = p;
    }
    __syncthreads();

    {
        float* rpg = rpout + (long)chunk * 64 * 64;
        #pragma unroll
        for (int e = 0; e < 16; e++) {
            int flat = tid + 256 * e;
            rpg[flat] = rpT[(flat >> 6) * STRD + (flat & 63)];
        }
    }

    {
        int t0 = (tid >> 4) * 4, s0 = (tid & 15) * 4;
        float acc[4][4];
        #pragma unroll
        for (int a = 0; a < 4; a++)
            #pragma unroll
            for (int bq = 0; bq < 4; bq++) acc[a][bq] = 0.f;
        for (int ii = 0; ii < 64; ii++) {
            float4 a4 = *(const float4*)&rpT[ii * STRD + t0];
            float4 b4 = *(const float4*)&kpT[ii * STRD + s0];
            float av[4] = { a4.x, a4.y, a4.z, a4.w };
            float bv[4] = { b4.x, b4.y, b4.z, b4.w };
            #pragma unroll
            for (int a = 0; a < 4; a++)
                #pragma unroll
                for (int bq = 0; bq < 4; bq++)
                    acc[a][bq] = fmaf(av[a], bv[bq], acc[a][bq]);
        }
        __syncthreads();
        #pragma unroll
        for (int a = 0; a < 4; a++)
            #pragma unroll
            for (int bq = 0; bq < 4; bq++) {
                int tt = t0 + a, ss = s0 + bq;
                float val = (tt > ss) ? acc[a][bq] : ((tt == ss) ? dsm[tt] : 0.f);
                bufA[ss * STRD + tt] = val;
            }
    }
    __syncthreads();

    {
        int t0 = (tid >> 4) * 4, j0 = (tid & 15) * 4;
        float acc[4][4];
        #pragma unroll
        for (int a = 0; a < 4; a++)
            #pragma unroll
            for (int bq = 0; bq < 4; bq++) acc[a][bq] = 0.f;
        for (int s = 0; s < 64; s++) {
            float4 a4 = *(const float4*)&bufA[s * STRD + t0];
            float4 b4 = *(const float4*)&vsm[s * STRD + j0];
            float av[4] = { a4.x, a4.y, a4.z, a4.w };
            float bv[4] = { b4.x, b4.y, b4.z, b4.w };
            #pragma unroll
            for (int a = 0; a < 4; a++)
                #pragma unroll
                for (int bq = 0; bq < 4; bq++)
                    acc[a][bq] = fmaf(av[a], bv[bq], acc[a][bq]);
        }
        #pragma unroll
        for (int a = 0; a < 4; a++) {
            float4 o = make_float4(acc[a][0], acc[a][1], acc[a][2], acc[a][3]);
            *(float4*)&y[base + (long)(t0 + a) * C_ + j0] = o;
        }
    }

    {
        int i0 = (tid >> 4) * 4, j0 = (tid & 15) * 4;
        float acc[4][4];
        #pragma unroll
        for (int a = 0; a < 4; a++)
            #pragma unroll
            for (int bq = 0; bq < 4; bq++) acc[a][bq] = 0.f;
        for (int s = 0; s < 64; s++) {
            float4 a4 = *(const float4*)&kpp[s * STRD + i0];
            float4 b4 = *(const float4*)&vsm[s * STRD + j0];
            float av[4] = { a4.x, a4.y, a4.z, a4.w };
            float bv[4] = { b4.x, b4.y, b4.z, b4.w };
            #pragma unroll
            for (int a = 0; a < 4; a++)
                #pragma unroll
                for (int bq = 0; bq < 4; bq++)
                    acc[a][bq] = fmaf(av[a], bv[bq], acc[a][bq]);
        }
        float* Dp = Dout + (long)chunk * 4096;
        #pragma unroll
        for (int a = 0; a < 4; a++) {
            float4 o = make_float4(acc[a][0], acc[a][1], acc[a][2], acc[a][3]);
            *(float4*)&Dp[(i0 + a) * 64 + j0] = o;
        }
    }
}

__global__ __launch_bounds__(256) void wkv_chunkB(
    const float* __restrict__ D, const float* __restrict__ pL,
    float* __restrict__ S)
{
    const int bh = blockIdx.x;
    const int tid = threadIdx.x;
    const int i = tid >> 2;
    const int jb = (tid & 3) * 16;
    float4 s0 = {0,0,0,0}, s1 = {0,0,0,0}, s2 = {0,0,0,0}, s3 = {0,0,0,0};
    for (int c = 0; c < G_; c++) {
        long chunk = (long)bh * G_ + c;
        long off = chunk * 4096 + i * 64 + jb;
        *(float4*)&S[off + 0]  = s0;
        *(float4*)&S[off + 4]  = s1;
        *(float4*)&S[off + 8]  = s2;
        *(float4*)&S[off + 12] = s3;
        float pl = __expf(pL[chunk * 64 + i]);
        float4 d0 = *(const float4*)&D[off + 0];
        float4 d1 = *(const float4*)&D[off + 4];
        float4 d2 = *(const float4*)&D[off + 8];
        float4 d3 = *(const float4*)&D[off + 12];
        s0 = make_float4(fmaf(pl, s0.x, d0.x), fmaf(pl, s0.y, d0.y), fmaf(pl, s0.z, d0.z), fmaf(pl, s0.w, d0.w));
        s1 = make_float4(fmaf(pl, s1.x, d1.x), fmaf(pl, s1.y, d1.y), fmaf(pl, s1.z, d1.z), fmaf(pl, s1.w, d1.w));
        s2 = make_float4(fmaf(pl, s2.x, d2.x), fmaf(pl, s2.y, d2.y), fmaf(pl, s2.z, d2.z), fmaf(pl, s2.w, d2.w));
        s3 = make_float4(fmaf(pl, s3.x, d3.x), fmaf(pl, s3.y, d3.y), fmaf(pl, s3.z, d3.z), fmaf(pl, s3.w, d3.w));
    }
}

__global__ __launch_bounds__(256) void wkv_chunkC(
    const float* __restrict__ rp, const float* __restrict__ S,
    float* __restrict__ y)
{
    __shared__ float rps[64 * 64];
    __shared__ float Ss[64 * 64];
    const int tid = threadIdx.x;
    const int chunk = blockIdx.x;
    const int bh = chunk >> 5;
    const int c  = chunk & 31;
    const int b = bh >> 4, h = bh & 15;
    const long base = ((long)b * T_ + c * CHUNK) * C_ + h * 64;

    const float* rpg = rp + (long)chunk * 4096;
    const float* Sg  = S  + (long)chunk * 4096;
    #pragma unroll
    for (int e = 0; e < 4; e++) {
        int f4 = tid + 256 * e;
        *(float4*)&rps[f4 * 4] = *(const float4*)&rpg[f4 * 4];
        *(float4*)&Ss[f4 * 4]  = *(const float4*)&Sg[f4 * 4];
    }
    __syncthreads();

    int t0 = (tid >> 4) * 4, j0 = (tid & 15) * 4;
    float acc[4][4];
    #pragma unroll
    for (int a = 0; a < 4; a++)
        #pragma unroll
        for (int bq = 0; bq < 4; bq++) acc[a][bq] = 0.f;
    for (int ii = 0; ii < 64; ii++) {
        float4 a4 = *(const float4*)&rps[ii * 64 + t0];
        float4 b4 = *(const float4*)&Ss[ii * 64 + j0];
        float av[4] = { a4.x, a4.y, a4.z, a4.w };
        float bv[4] = { b4.x, b4.y, b4.z, b4.w };
        #pragma unroll
        for (int a = 0; a < 4; a++)
            #pragma unroll
            for (int bq = 0; bq < 4; bq++)
                acc[a][bq] = fmaf(av[a], bv[bq], acc[a][bq]);
    }
    #pragma unroll
    for (int a = 0; a < 4; a++) {
        long yo = base + (long)(t0 + a) * C_ + j0;
        float4 cur = *(const float4*)&y[yo];
        cur.x += acc[a][0]; cur.y += acc[a][1];
        cur.z += acc[a][2]; cur.w += acc[a][3];
        *(float4*)&y[yo] = cur;
    }
}

// ---------------- GroupNorm over heads + gate multiply -----------------------
__global__ __launch_bounds__(512) void gn_kernel(
    const float* __restrict__ y, const float* __restrict__ ln_g,
    const float* __restrict__ ln_b, const float* __restrict__ g,
    float* __restrict__ z)
{
    const int bt = blockIdx.x;
    const int warp = threadIdx.x >> 5;
    const int lane = threadIdx.x & 31;
    const long base = (long)bt * C_ + warp * 64;

    float a0 = y[base + lane];
    float a1 = y[base + 32 + lane];
    float sum = a0 + a1;
    float sq = a0 * a0 + a1 * a1;
    #pragma unroll
    for (int off = 16; off > 0; off >>= 1) {
        sum += __shfl_xor_sync(0xffffffffu, sum, off);
        sq  += __shfl_xor_sync(0xffffffffu, sq,  off);
    }
    float mu = sum * (1.f / 64.f);
    float var = sq * (1.f / 64.f) - mu * mu;
    float inv = rsqrtf(var + 6.4e-4f);

    int c0 = warp * 64 + lane;
    float z0 = (a0 - mu) * inv * ln_g[c0] + ln_b[c0];
    float z1 = (a1 - mu) * inv * ln_g[c0 + 32] + ln_b[c0 + 32];
    z[base + lane]      = z0 * g[base + lane];
    z[base + 32 + lane] = z1 * g[base + 32 + lane];
}

// ---------------- launcher ----------------------------------------------------
extern "C" void kernel_launch(void* const* d_in, const int* in_sizes, int n_in,
                              void* d_out, int out_size)
{
    const float* x          = (const float*)d_in[0];
    const float* maa_x      = (const float*)d_in[1];
    const float* maa_w      = (const float*)d_in[2];
    const float* maa_k      = (const float*)d_in[3];
    const float* maa_v      = (const float*)d_in[4];
    const float* maa_r      = (const float*)d_in[5];
    const float* maa_g      = (const float*)d_in[6];
    const float* maa_w1     = (const float*)d_in[7];
    const float* maa_w2     = (const float*)d_in[8];
    const float* Wr         = (const float*)d_in[9];
    const float* Wk         = (const float*)d_in[10];
    const float* Wv         = (const float*)d_in[11];
    const float* Wo         = (const float*)d_in[12];
    const float* gate_w1    = (const float*)d_in[13];
    const float* gate_w2    = (const float*)d_in[14];
    const float* time_decay = (const float*)d_in[15];
    const float* decay_w1   = (const float*)d_in[16];
    const float* decay_w2   = (const float*)d_in[17];
    const float* u          = (const float*)d_in[18];
    const float* ln_g       = (const float*)d_in[19];
    const float* ln_b       = (const float*)d_in[20];
    (void)in_sizes; (void)n_in; (void)out_size;

    float *p_xx, *p_xxx, *p_xw, *p_xk, *p_xv, *p_xr, *p_xg;
    float *p_r, *p_k, *p_v, *p_w, *p_g, *p_y, *p_z, *p_lora, *p_small;
    float *p_D, *p_Sc, *p_rp, *p_pL;
    float *p_WrT, *p_WkT, *p_WvT, *p_WoT, *p_w1T, *p_w2T, *p_dw1T, *p_gw1T, *p_dw2T, *p_gw2T;
    cudaGetSymbolAddress((void**)&p_xx, g_xx);
    cudaGetSymbolAddress((void**)&p_xxx, g_xxx);
    cudaGetSymbolAddress((void**)&p_xw, g_xw);
    cudaGetSymbolAddress((void**)&p_xk, g_xk);
    cudaGetSymbolAddress((void**)&p_xv, g_xv);
    cudaGetSymbolAddress((void**)&p_xr, g_xr);
    cudaGetSymbolAddress((void**)&p_xg, g_xg);
    cudaGetSymbolAddress((void**)&p_r, g_r);
    cudaGetSymbolAddress((void**)&p_k, g_k);
    cudaGetSymbolAddress((void**)&p_v, g_v);
    cudaGetSymbolAddress((void**)&p_w, g_w);
    cudaGetSymbolAddress((void**)&p_g, g_g);
    cudaGetSymbolAddress((void**)&p_y, g_y);
    cudaGetSymbolAddress((void**)&p_z, g_z);
    cudaGetSymbolAddress((void**)&p_lora, g_lora);
    cudaGetSymbolAddress((void**)&p_small, g_small);
    cudaGetSymbolAddress((void**)&p_D, g_D);
    cudaGetSymbolAddress((void**)&p_Sc, g_Sc);
    cudaGetSymbolAddress((void**)&p_rp, g_rp);
    cudaGetSymbolAddress((void**)&p_pL, g_pL);
    cudaGetSymbolAddress((void**)&p_WrT, g_WrT);
    cudaGetSymbolAddress((void**)&p_WkT, g_WkT);
    cudaGetSymbolAddress((void**)&p_WvT, g_WvT);
    cudaGetSymbolAddress((void**)&p_WoT, g_WoT);
    cudaGetSymbolAddress((void**)&p_w1T, g_w1T);
    cudaGetSymbolAddress((void**)&p_w2T, g_w2T);
    cudaGetSymbolAddress((void**)&p_dw1T, g_dw1T);
    cudaGetSymbolAddress((void**)&p_gw1T, g_gw1T);
    cudaGetSymbolAddress((void**)&p_dw2T, g_dw2T);
    cudaGetSymbolAddress((void**)&p_gw2T, g_gw2T);

    const long total = BTC;
    const int M = B_ * T_;          // 8192
    const int gy = M / 128;         // 64
    const int gy64 = M / 64;        // 128

    const int SMEM_A = (65 * 64 + 5 * 64 * STRD + 128) * 4;
    cudaFuncSetAttribute(wkv_chunkA, cudaFuncAttributeMaxDynamicSharedMemorySize, SMEM_A);

    const float* maas[5] = { maa_w, maa_k, maa_v, maa_r, maa_g };
    float* xouts[5] = { p_xw, p_xk, p_xv, p_xr, p_xg };

    // 0. time shift + maa_x mix
    shift_kernel<<<(int)((total + 255) / 256), 256>>>(x, maa_x, p_xx, p_xxx, total);
    // 1. transpose maa_w1 [1024,160] -> [160,1024]
    transpose_k<<<dim3(5, 32), dim3(32, 8)>>>(maa_w1, p_w1T, C_, 160);
    // 2. lora = tanh(xxx @ maa_w1)  N=160
    gemm_tc64<1><<<dim3(3, gy64), 128>>>(p_xxx, C_, p_w1T, C_, p_lora, 160, C_, 160, nullptr);
    // 3. transpose maa_w2 (viewed [160,1024]) -> [1024,160]
    transpose_k<<<dim3(32, 5), dim3(32, 8)>>>(maa_w2, p_w2T, 160, C_);
    // 4. transpose Wr
    transpose_k<<<dim3(32, 32), dim3(32, 8)>>>(Wr, p_WrT, C_, C_);
    // 5..9. mix GEMMs with fused token-shift blend epilogue (launch 5 profiled)
    for (int f = 0; f < 5; f++)
        gemm_tc<3><<<dim3(8, gy), 256>>>(p_lora + f * DMIX, 160,
                                         p_w2T + f * DMIX, 160,
                                         xouts[f], C_, DMIX, C_,
                                         maas[f], x, p_xx);
    // 10. r projection
    gemm_tc<0><<<dim3(8, gy), 256>>>(p_xr, C_, p_WrT, C_, p_r, C_, C_, C_, nullptr, nullptr, nullptr);
    // k, v projections
    transpose_k<<<dim3(32, 32), dim3(32, 8)>>>(Wk, p_WkT, C_, C_);
    gemm_tc<0><<<dim3(8, gy), 256>>>(p_xk, C_, p_WkT, C_, p_k, C_, C_, C_, nullptr, nullptr, nullptr);
    transpose_k<<<dim3(32, 32), dim3(32, 8)>>>(Wv, p_WvT, C_, C_);
    gemm_tc<0><<<dim3(8, gy), 256>>>(p_xv, C_, p_WvT, C_, p_v, C_, C_, C_, nullptr, nullptr, nullptr);
    // decay: lw = -exp(time_decay + tanh(xw@decay_w1)@decay_w2)
    transpose_k<<<dim3(2, 32), dim3(32, 8)>>>(decay_w1, p_dw1T, C_, 64);
    gemm_tc64<1><<<dim3(1, gy64), 128>>>(p_xw, C_, p_dw1T, C_, p_small, 64, C_, 64, nullptr);
    transpose_k<<<dim3(32, 2), dim3(32, 8)>>>(decay_w2, p_dw2T, 64, C_);
    gemm_tc<2><<<dim3(8, gy), 256>>>(p_small, 64, p_dw2T, 64, p_w, C_, 64, C_, time_decay, nullptr, nullptr);
    // chunked WKV6
    wkv_chunkA<<<NCHUNK, 256, SMEM_A>>>(p_r, p_k, p_v, p_w, u,
                                        p_y, p_D, p_rp, p_pL);
    wkv_chunkB<<<B_ * H_, 256>>>(p_D, p_pL, p_Sc);
    wkv_chunkC<<<NCHUNK, 256>>>(p_rp, p_Sc, p_y);
    // gate
    transpose_k<<<dim3(2, 32), dim3(32, 8)>>>(gate_w1,  p_gw1T, C_, 64);
    gemm_tc64<1><<<dim3(1, gy64), 128>>>(p_xg, C_, p_gw1T, C_, p_small, 64, C_, 64, nullptr);
    transpose_k<<<dim3(32, 2), dim3(32, 8)>>>(gate_w2,  p_gw2T, 64, C_);
    gemm_tc<0><<<dim3(8, gy), 256>>>(p_small, 64, p_gw2T, 64, p_g, C_, 64, C_, nullptr, nullptr, nullptr);
    // GroupNorm + gate multiply
    gn_kernel<<<M, 512>>>(p_y, ln_g, ln_b, p_g, p_z);
    // out = z @ Wo
    transpose_k<<<dim3(32, 32), dim3(32, 8)>>>(Wo, p_WoT, C_, C_);
    gemm_tc<0><<<dim3(8, gy), 256>>>(p_z, C_, p_WoT, C_, (float*)d_out, C_, C_, C_, nullptr, nullptr, nullptr);
}